// round 1
// baseline (speedup 1.0000x reference)
#include <cuda_runtime.h>
#include <cuda_bf16.h>
#include <math.h>

// Problem constants
#define BATCH 4
#define DIM 128
#define HH 128
#define WW 128
#define HW (HH*WW)           // 16384
#define NP (BATCH*HW)        // 65536 pixels
#define HID 512
#define GC1 32
#define GC2 64
#define GC3 32

// ---------------- scratch (static device globals; no runtime alloc) -------------
__device__ float g_off[BATCH*18*HW];          // offsets [b,18,h,w]
__device__ float g_y[BATCH*DIM*HW];           // shuffled concat, NCHW
__device__ float g_t[(size_t)NP*HID];         // MLP hidden
__device__ float g_c2[(size_t)NP*DIM];        // MLP out, (pixel, channel)
__device__ float g_bn1_sum[BATCH*DIM];
__device__ float g_bn1_sq [BATCH*DIM];
__device__ float g_scale1[DIM], g_shift1[DIM];
__device__ float g_bn2_sum[256*DIM];
__device__ float g_bn2_sq [256*DIM];
__device__ float g_scale2[DIM], g_shift2[DIM];

__device__ __forceinline__ float gelu_exact(float v) {
    return 0.5f * v * (1.0f + erff(v * 0.70710678118654752440f));
}

// ---------------- offset conv: 3x3, 32->18, pad 1 ----------------
__global__ void k_offset_conv(const float* __restrict__ x,
                              const float* __restrict__ ow,
                              const float* __restrict__ ob) {
    int b  = blockIdx.z;
    int oc = blockIdx.y;
    int hw = blockIdx.x * 256 + threadIdx.x;
    __shared__ float w[GC1*9];
    for (int i = threadIdx.x; i < GC1*9; i += 256) w[i] = ow[oc*GC1*9 + i];
    __syncthreads();
    int h = hw >> 7, wcol = hw & 127;
    float acc = ob[oc];
    const float* xb = x + (size_t)b*DIM*HW;
    for (int ic = 0; ic < GC1; ic++) {
        const float* xp = xb + ic*HW;
        const float* wk = w + ic*9;
        #pragma unroll
        for (int ky = 0; ky < 3; ky++) {
            int yy = h + ky - 1;
            if (yy < 0 || yy > 127) continue;
            #pragma unroll
            for (int kx = 0; kx < 3; kx++) {
                int xx = wcol + kx - 1;
                if (xx < 0 || xx > 127) continue;
                acc += xp[yy*WW + xx] * wk[ky*3 + kx];
            }
        }
    }
    g_off[((size_t)b*18 + oc)*HW + hw] = acc;
}

// ---------------- deformable depthwise 3x3 on channels 0..31 ----------------
// old channel c (0..31) -> new channel 2c
__global__ void k_deform(const float* __restrict__ x,
                         const float* __restrict__ dfw) {
    int b = blockIdx.z;
    int c = blockIdx.y;
    int hw = blockIdx.x * 256 + threadIdx.x;
    __shared__ float wk[9];
    if (threadIdx.x < 9) wk[threadIdx.x] = dfw[c*9 + threadIdx.x];
    __syncthreads();
    int h = hw >> 7, wcol = hw & 127;
    const float* xp = x + ((size_t)b*DIM + c)*HW;
    const float* offb = g_off + (size_t)b*18*HW;
    float acc = 0.f;
    #pragma unroll
    for (int k = 0; k < 9; k++) {
        float dy = offb[(2*k  )*HW + hw];
        float dx = offb[(2*k+1)*HW + hw];
        float ys = (float)h - 1.0f + (float)(k/3) + dy;
        float xs = (float)wcol - 1.0f + (float)(k%3) + dx;
        float y0 = floorf(ys), x0 = floorf(xs);
        float sv = 0.f;
        #pragma unroll
        for (int dyb = 0; dyb < 2; dyb++) {
            #pragma unroll
            for (int dxb = 0; dxb < 2; dxb++) {
                float yc = y0 + dyb, xc = x0 + dxb;
                float wt = (1.0f - fabsf(ys - yc)) * (1.0f - fabsf(xs - xc));
                bool valid = (yc >= 0.f) && (yc <= 127.f) && (xc >= 0.f) && (xc <= 127.f);
                if (valid) {
                    int yi = (int)yc, xi = (int)xc;
                    sv += xp[yi*WW + xi] * wt;
                }
            }
        }
        acc += sv * wk[k];
    }
    g_y[((size_t)b*DIM + 2*c)*HW + hw] = acc;
}

// ---------------- depthwise 7x7 on channels 32..95 ----------------
// weight channel j (0..63), old channel = 32+j
// new channel = (old<64) ? 2*old : 2*(old-64)+1
__global__ void k_dw7(const float* __restrict__ x,
                      const float* __restrict__ dww,
                      const float* __restrict__ dwb) {
    int b = blockIdx.z;
    int c = blockIdx.y;  // 0..63
    int hw = blockIdx.x * 256 + threadIdx.x;
    __shared__ float w[49];
    if (threadIdx.x < 49) w[threadIdx.x] = dww[c*49 + threadIdx.x];
    __syncthreads();
    int h = hw >> 7, wcol = hw & 127;
    const float* xp = x + ((size_t)b*DIM + 32 + c)*HW;
    float acc = dwb[c];
    #pragma unroll
    for (int ky = 0; ky < 7; ky++) {
        int yy = h + ky - 3;
        if (yy < 0 || yy > 127) continue;
        #pragma unroll
        for (int kx = 0; kx < 7; kx++) {
            int xx = wcol + kx - 3;
            if (xx < 0 || xx > 127) continue;
            acc += xp[yy*WW + xx] * w[ky*7 + kx];
        }
    }
    int oldc = 32 + c;
    int newc = (oldc < 64) ? (2*oldc) : (2*(oldc-64)+1);
    g_y[((size_t)b*DIM + newc)*HW + hw] = acc;
}

// ---------------- dilated 3x3 conv 32->32 (dilation=2, pad=2), channels 96..127 --
// old channel = 96+oc -> new channel 2*(96+oc-64)+1 = 65+2*oc
__global__ void k_dil3(const float* __restrict__ x,
                       const float* __restrict__ w2w,
                       const float* __restrict__ w2b) {
    int b  = blockIdx.z;
    int oc = blockIdx.y;
    int hw = blockIdx.x * 256 + threadIdx.x;
    __shared__ float w[GC3*9];
    for (int i = threadIdx.x; i < GC3*9; i += 256) w[i] = w2w[oc*GC3*9 + i];
    __syncthreads();
    int h = hw >> 7, wcol = hw & 127;
    float acc = w2b[oc];
    const float* xb = x + ((size_t)b*DIM + 96)*HW;
    for (int ic = 0; ic < GC3; ic++) {
        const float* xp = xb + ic*HW;
        const float* wk = w + ic*9;
        #pragma unroll
        for (int ky = 0; ky < 3; ky++) {
            int yy = h + 2*ky - 2;
            if (yy < 0 || yy > 127) continue;
            #pragma unroll
            for (int kx = 0; kx < 3; kx++) {
                int xx = wcol + 2*kx - 2;
                if (xx < 0 || xx > 127) continue;
                acc += xp[yy*WW + xx] * wk[ky*3 + kx];
            }
        }
    }
    g_y[((size_t)b*DIM + 65 + 2*oc)*HW + hw] = acc;
}

// ---------------- BN1 partial: one block per (b,c), deterministic ----------------
__global__ void k_bn1_part() {
    int bc = blockIdx.x; // 0..511
    const float* p = g_y + (size_t)bc*HW;
    float s = 0.f, q = 0.f;
    for (int i = threadIdx.x; i < HW; i += 256) {
        float v = p[i]; s += v; q += v*v;
    }
    __shared__ float ss[256], qs[256];
    ss[threadIdx.x] = s; qs[threadIdx.x] = q;
    __syncthreads();
    for (int st = 128; st > 0; st >>= 1) {
        if (threadIdx.x < st) { ss[threadIdx.x] += ss[threadIdx.x+st]; qs[threadIdx.x] += qs[threadIdx.x+st]; }
        __syncthreads();
    }
    if (threadIdx.x == 0) { g_bn1_sum[bc] = ss[0]; g_bn1_sq[bc] = qs[0]; }
}

__global__ void k_bn1_final(const float* __restrict__ g, const float* __restrict__ be) {
    int c = threadIdx.x;
    float s = 0.f, q = 0.f;
    #pragma unroll
    for (int b = 0; b < BATCH; b++) { s += g_bn1_sum[b*DIM + c]; q += g_bn1_sq[b*DIM + c]; }
    float mean = s * (1.0f/NP);
    float var  = q * (1.0f/NP) - mean*mean;
    float rstd = rsqrtf(var + 1e-5f);
    float sc = g[c] * rstd;
    g_scale1[c] = sc;
    g_shift1[c] = be[c] - mean * sc;
}

// ---------------- GEMM1: [NP,128] x [128,512] + b1, gelu -> g_t ----------------
// A read column-major directly from NCHW g_y with fused BN1 normalize.
__global__ void k_gemm1(const float* __restrict__ w1, const float* __restrict__ b1) {
    __shared__ float As[16][64];
    __shared__ float Bs[16][64];
    int tx = threadIdx.x, ty = threadIdx.y;
    int tid = ty*16 + tx;
    int p0 = blockIdx.y * 64;
    int n0 = blockIdx.x * 64;
    int b  = p0 >> 14;
    int hw0 = p0 & 16383;
    float acc[4][4] = {};
    for (int kt = 0; kt < DIM; kt += 16) {
        #pragma unroll
        for (int l = 0; l < 4; l++) {
            int e = tid + l*256;
            int c = e >> 6, r = e & 63;
            int ch = kt + c;
            float v = g_y[((size_t)b*DIM + ch)*HW + hw0 + r];
            As[c][r] = v * g_scale1[ch] + g_shift1[ch];
        }
        #pragma unroll
        for (int l = 0; l < 4; l++) {
            int e = tid + l*256;
            int kr = e >> 6, n = e & 63;
            Bs[kr][n] = w1[(kt + kr)*HID + n0 + n];
        }
        __syncthreads();
        #pragma unroll
        for (int k = 0; k < 16; k++) {
            float a[4], bb[4];
            #pragma unroll
            for (int i = 0; i < 4; i++) a[i]  = As[k][ty + i*16];
            #pragma unroll
            for (int j = 0; j < 4; j++) bb[j] = Bs[k][tx + j*16];
            #pragma unroll
            for (int i = 0; i < 4; i++)
                #pragma unroll
                for (int j = 0; j < 4; j++)
                    acc[i][j] += a[i] * bb[j];
        }
        __syncthreads();
    }
    #pragma unroll
    for (int i = 0; i < 4; i++) {
        int p = p0 + ty + i*16;
        #pragma unroll
        for (int j = 0; j < 4; j++) {
            int n = n0 + tx + j*16;
            g_t[(size_t)p*HID + n] = gelu_exact(acc[i][j] + b1[n]);
        }
    }
}

// ---------------- GEMM2: [NP,512] x [512,128] + b2 -> g_c2 ----------------
__global__ void k_gemm2(const float* __restrict__ w2, const float* __restrict__ b2) {
    __shared__ float As[16][65];
    __shared__ float Bs[16][64];
    int tx = threadIdx.x, ty = threadIdx.y;
    int tid = ty*16 + tx;
    int p0 = blockIdx.y * 64;
    int n0 = blockIdx.x * 64;
    float acc[4][4] = {};
    for (int kt = 0; kt < HID; kt += 16) {
        #pragma unroll
        for (int l = 0; l < 4; l++) {
            int e = tid + l*256;
            int r = e >> 4, kk = e & 15;
            As[kk][r] = g_t[(size_t)(p0 + r)*HID + kt + kk];
        }
        #pragma unroll
        for (int l = 0; l < 4; l++) {
            int e = tid + l*256;
            int kr = e >> 6, n = e & 63;
            Bs[kr][n] = w2[(kt + kr)*DIM + n0 + n];
        }
        __syncthreads();
        #pragma unroll
        for (int k = 0; k < 16; k++) {
            float a[4], bb[4];
            #pragma unroll
            for (int i = 0; i < 4; i++) a[i]  = As[k][ty + i*16];
            #pragma unroll
            for (int j = 0; j < 4; j++) bb[j] = Bs[k][tx + j*16];
            #pragma unroll
            for (int i = 0; i < 4; i++)
                #pragma unroll
                for (int j = 0; j < 4; j++)
                    acc[i][j] += a[i] * bb[j];
        }
        __syncthreads();
    }
    #pragma unroll
    for (int i = 0; i < 4; i++) {
        int p = p0 + ty + i*16;
        #pragma unroll
        for (int j = 0; j < 4; j++) {
            int n = n0 + tx + j*16;
            g_c2[(size_t)p*DIM + n] = acc[i][j] + b2[n];
        }
    }
}

// ---------------- BN2 partials over g_c2 columns (deterministic) ----------------
__global__ void k_bn2_part() {
    int c = threadIdx.x;        // 0..127
    int r0 = blockIdx.x * 256;  // 256 blocks
    float s = 0.f, q = 0.f;
    for (int r = r0; r < r0 + 256; r++) {
        float v = g_c2[(size_t)r*DIM + c];
        s += v; q += v*v;
    }
    g_bn2_sum[blockIdx.x*DIM + c] = s;
    g_bn2_sq [blockIdx.x*DIM + c] = q;
}

__global__ void k_bn2_final(const float* __restrict__ g, const float* __restrict__ be) {
    int c = threadIdx.x;
    float s = 0.f, q = 0.f;
    for (int i = 0; i < 256; i++) { s += g_bn2_sum[i*DIM + c]; q += g_bn2_sq[i*DIM + c]; }
    float mean = s * (1.0f/NP);
    float var  = q * (1.0f/NP) - mean*mean;
    float rstd = rsqrtf(var + 1e-5f);
    float sc = g[c] * rstd;
    g_scale2[c] = sc;
    g_shift2[c] = be[c] - mean * sc;
}

// ---------------- final: transpose (p,c)->NCHW fused BN2 + residual + gelu ------
__global__ void k_final(const float* __restrict__ x, float* __restrict__ out) {
    __shared__ float sm[32][33];
    int b   = blockIdx.z;
    int c0  = blockIdx.y * 32;
    int hw0 = blockIdx.x * 32;
    int tx = threadIdx.x, ty = threadIdx.y;
    sm[ty][tx] = g_c2[(size_t)(b*HW + hw0 + ty)*DIM + c0 + tx];
    __syncthreads();
    int c = c0 + ty;
    int hw = hw0 + tx;
    float v = sm[tx][ty] * g_scale2[c] + g_shift2[c];
    size_t idx = ((size_t)(b*DIM + c))*HW + hw;
    out[idx] = gelu_exact(x[idx] + v);
}

// ================================ launch ================================
extern "C" void kernel_launch(void* const* d_in, const int* in_sizes, int n_in,
                              void* d_out, int out_size) {
    const float* x        = (const float*)d_in[0];
    const float* offset_w = (const float*)d_in[1];
    const float* offset_b = (const float*)d_in[2];
    const float* deform_w = (const float*)d_in[3];
    const float* dw_w     = (const float*)d_in[4];
    const float* dw_b     = (const float*)d_in[5];
    const float* dw2_w    = (const float*)d_in[6];
    const float* dw2_b    = (const float*)d_in[7];
    const float* bn1_g    = (const float*)d_in[8];
    const float* bn1_b    = (const float*)d_in[9];
    const float* w1       = (const float*)d_in[10];
    const float* b1       = (const float*)d_in[11];
    const float* w2       = (const float*)d_in[12];
    const float* b2       = (const float*)d_in[13];
    const float* bn2_g    = (const float*)d_in[14];
    const float* bn2_b    = (const float*)d_in[15];
    float* out = (float*)d_out;

    dim3 blk256(256);
    k_offset_conv<<<dim3(HW/256, 18, BATCH), blk256>>>(x, offset_w, offset_b);
    k_deform     <<<dim3(HW/256, GC1, BATCH), blk256>>>(x, deform_w);
    k_dw7        <<<dim3(HW/256, GC2, BATCH), blk256>>>(x, dw_w, dw_b);
    k_dil3       <<<dim3(HW/256, GC3, BATCH), blk256>>>(x, dw2_w, dw2_b);

    k_bn1_part <<<BATCH*DIM, blk256>>>();
    k_bn1_final<<<1, DIM>>>(bn1_g, bn1_b);

    dim3 gblk(16, 16);
    k_gemm1<<<dim3(HID/64, NP/64), gblk>>>(w1, b1);
    k_gemm2<<<dim3(DIM/64, NP/64), gblk>>>(w2, b2);

    k_bn2_part <<<256, DIM>>>();
    k_bn2_final<<<1, DIM>>>(bn2_g, bn2_b);

    k_final<<<dim3(HW/32, DIM/32, BATCH), dim3(32, 32)>>>(x, out);
}

// round 3
// speedup vs baseline: 1.9735x; 1.9735x over previous
#include <cuda_runtime.h>
#include <cuda_bf16.h>
#include <math.h>
#include <stdint.h>

#define BATCH 4
#define DIM 128
#define HH 128
#define WW 128
#define HW (HH*WW)           // 16384
#define NP (BATCH*HW)        // 65536
#define HID 512
#define GC1 32
#define GC2 64
#define GC3 32

// ---------------- scratch ----------------
__device__ float g_off[BATCH*18*HW];
__device__ float g_y[BATCH*DIM*HW];            // shuffled concat, NCHW
__device__ float g_t[(size_t)HID*NP];          // GEMM1 out, TRANSPOSED [HID][NP]
__device__ float g_c2[(size_t)DIM*NP];         // GEMM2 out, TRANSPOSED [DIM][NP]
__device__ float g_w1f[DIM*HID];               // BN1-folded w1
__device__ float g_b1f[HID];
__device__ float g_bn1_sum[BATCH*DIM];
__device__ float g_bn1_sq [BATCH*DIM];
__device__ float g_scale1[DIM], g_shift1[DIM];
__device__ float g_bn2_sum[8*DIM];
__device__ float g_bn2_sq [8*DIM];
__device__ float g_scale2[DIM], g_shift2[DIM];

__device__ __forceinline__ float gelu_exact(float v) {
    return 0.5f * v * (1.0f + erff(v * 0.70710678118654752440f));
}
__device__ __forceinline__ uint32_t f2tf32(float f) {
    uint32_t r;
    asm("cvt.rna.tf32.f32 %0, %1;" : "=r"(r) : "f"(f));
    return r;
}
__device__ __forceinline__ void mma_tf32(float* c, const uint32_t* a, const uint32_t* b) {
    asm volatile("mma.sync.aligned.m16n8k8.row.col.f32.tf32.tf32.f32 "
        "{%0,%1,%2,%3}, {%4,%5,%6,%7}, {%8,%9}, {%0,%1,%2,%3};"
        : "+f"(c[0]), "+f"(c[1]), "+f"(c[2]), "+f"(c[3])
        : "r"(a[0]), "r"(a[1]), "r"(a[2]), "r"(a[3]), "r"(b[0]), "r"(b[1]));
}

#define KSTR 136   // smem row stride (floats): conflict-free frags + aligned STS.64
#define TSTR 130   // epilogue transpose stride

// ======================= conv kernels =======================

// offset conv 3x3 pad1, 32->18, smem tile 32x32 (+1 halo), 6 oc per block
__global__ __launch_bounds__(256) void k_offset_v2(const float* __restrict__ x,
                                                   const float* __restrict__ ow,
                                                   const float* __restrict__ ob) {
    __shared__ float s[4*34*34];
    __shared__ float ws[6*4*9];
    int tid = threadIdx.x;
    int b = blockIdx.z;
    int oc0 = blockIdx.y * 6;
    int ty0 = (blockIdx.x >> 2) * 32, tx0 = (blockIdx.x & 3) * 32;
    float acc[6][4] = {};
    for (int icc = 0; icc < 8; icc++) {
        int ic0 = icc * 4;
        const float* xb = x + ((size_t)b*DIM + ic0)*HW;
        for (int i = tid; i < 4*34*34; i += 256) {
            int icl = i / 1156, e = i % 1156;
            int sy = e / 34, sx = e % 34;
            int gy = ty0 + sy - 1, gx = tx0 + sx - 1;
            float v = 0.f;
            if (gy >= 0 && gy < 128 && gx >= 0 && gx < 128) v = xb[(size_t)icl*HW + gy*WW + gx];
            s[i] = v;
        }
        for (int i = tid; i < 216; i += 256) {
            int ocl = i / 36, icl = (i % 36) / 9, k = i % 9;
            ws[i] = ow[(oc0+ocl)*(GC1*9) + (ic0+icl)*9 + k];
        }
        __syncthreads();
        #pragma unroll
        for (int icl = 0; icl < 4; icl++) {
            #pragma unroll
            for (int q = 0; q < 4; q++) {
                int p = tid + q*256;
                int ly = p >> 5, lx = p & 31;
                const float* sp = s + icl*1156 + ly*34 + lx;
                float t0 = sp[0],    t1 = sp[1],    t2 = sp[2];
                float t3 = sp[34],   t4 = sp[35],   t5 = sp[36];
                float t6 = sp[68],   t7 = sp[69],   t8 = sp[70];
                #pragma unroll
                for (int o = 0; o < 6; o++) {
                    const float* wp = ws + (o*4 + icl)*9;
                    acc[o][q] += t0*wp[0] + t1*wp[1] + t2*wp[2]
                               + t3*wp[3] + t4*wp[4] + t5*wp[5]
                               + t6*wp[6] + t7*wp[7] + t8*wp[8];
                }
            }
        }
        __syncthreads();
    }
    #pragma unroll
    for (int o = 0; o < 6; o++) {
        float bias = ob[oc0+o];
        #pragma unroll
        for (int q = 0; q < 4; q++) {
            int p = tid + q*256;
            int ly = p >> 5, lx = p & 31;
            g_off[((size_t)b*18 + oc0+o)*HW + (ty0+ly)*WW + tx0+lx] = acc[o][q] + bias;
        }
    }
}

// dilated 3x3 (d=2, pad=2), 32->32, smem tile 32x32 (+2 halo), 8 oc per block
__global__ __launch_bounds__(256) void k_dil3_v2(const float* __restrict__ x,
                                                 const float* __restrict__ w2w,
                                                 const float* __restrict__ w2b) {
    __shared__ float s[4*36*36];
    __shared__ float ws[8*4*9];
    int tid = threadIdx.x;
    int b = blockIdx.z;
    int oc0 = blockIdx.y * 8;
    int ty0 = (blockIdx.x >> 2) * 32, tx0 = (blockIdx.x & 3) * 32;
    float acc[8][4] = {};
    for (int icc = 0; icc < 8; icc++) {
        int ic0 = icc * 4;
        const float* xb = x + ((size_t)b*DIM + 96 + ic0)*HW;
        for (int i = tid; i < 4*36*36; i += 256) {
            int icl = i / 1296, e = i % 1296;
            int sy = e / 36, sx = e % 36;
            int gy = ty0 + sy - 2, gx = tx0 + sx - 2;
            float v = 0.f;
            if (gy >= 0 && gy < 128 && gx >= 0 && gx < 128) v = xb[(size_t)icl*HW + gy*WW + gx];
            s[i] = v;
        }
        for (int i = tid; i < 288; i += 256) {
            int ocl = i / 36, icl = (i % 36) / 9, k = i % 9;
            ws[i] = w2w[(oc0+ocl)*(GC3*9) + (ic0+icl)*9 + k];
        }
        __syncthreads();
        #pragma unroll
        for (int icl = 0; icl < 4; icl++) {
            #pragma unroll
            for (int q = 0; q < 4; q++) {
                int p = tid + q*256;
                int ly = p >> 5, lx = p & 31;
                const float* sp = s + icl*1296 + ly*36 + lx;
                float t0 = sp[0],     t1 = sp[2],     t2 = sp[4];
                float t3 = sp[72],    t4 = sp[74],    t5 = sp[76];
                float t6 = sp[144],   t7 = sp[146],   t8 = sp[148];
                #pragma unroll
                for (int o = 0; o < 8; o++) {
                    const float* wp = ws + (o*4 + icl)*9;
                    acc[o][q] += t0*wp[0] + t1*wp[1] + t2*wp[2]
                               + t3*wp[3] + t4*wp[4] + t5*wp[5]
                               + t6*wp[6] + t7*wp[7] + t8*wp[8];
                }
            }
        }
        __syncthreads();
    }
    #pragma unroll
    for (int o = 0; o < 8; o++) {
        float bias = w2b[oc0+o];
        int newc = 65 + 2*(oc0+o);
        #pragma unroll
        for (int q = 0; q < 4; q++) {
            int p = tid + q*256;
            int ly = p >> 5, lx = p & 31;
            g_y[((size_t)b*DIM + newc)*HW + (ty0+ly)*WW + tx0+lx] = acc[o][q] + bias;
        }
    }
}

// deformable depthwise
__global__ void k_deform(const float* __restrict__ x, const float* __restrict__ dfw) {
    int b = blockIdx.z;
    int c = blockIdx.y;
    int hw = blockIdx.x * 256 + threadIdx.x;
    __shared__ float wk[9];
    if (threadIdx.x < 9) wk[threadIdx.x] = dfw[c*9 + threadIdx.x];
    __syncthreads();
    int h = hw >> 7, wcol = hw & 127;
    const float* xp = x + ((size_t)b*DIM + c)*HW;
    const float* offb = g_off + (size_t)b*18*HW;
    float acc = 0.f;
    #pragma unroll
    for (int k = 0; k < 9; k++) {
        float dy = offb[(2*k  )*HW + hw];
        float dx = offb[(2*k+1)*HW + hw];
        float ys = (float)h - 1.0f + (float)(k/3) + dy;
        float xs = (float)wcol - 1.0f + (float)(k%3) + dx;
        float y0 = floorf(ys), x0 = floorf(xs);
        float sv = 0.f;
        #pragma unroll
        for (int dyb = 0; dyb < 2; dyb++)
            #pragma unroll
            for (int dxb = 0; dxb < 2; dxb++) {
                float yc = y0 + dyb, xc = x0 + dxb;
                float wt = (1.0f - fabsf(ys - yc)) * (1.0f - fabsf(xs - xc));
                if (yc >= 0.f && yc <= 127.f && xc >= 0.f && xc <= 127.f) {
                    sv += xp[(int)yc*WW + (int)xc] * wt;
                }
            }
        acc += sv * wk[k];
    }
    g_y[((size_t)b*DIM + 2*c)*HW + hw] = acc;
}

// depthwise 7x7
__global__ void k_dw7(const float* __restrict__ x, const float* __restrict__ dww,
                      const float* __restrict__ dwb) {
    int b = blockIdx.z;
    int c = blockIdx.y;
    int hw = blockIdx.x * 256 + threadIdx.x;
    __shared__ float w[49];
    if (threadIdx.x < 49) w[threadIdx.x] = dww[c*49 + threadIdx.x];
    __syncthreads();
    int h = hw >> 7, wcol = hw & 127;
    const float* xp = x + ((size_t)b*DIM + 32 + c)*HW;
    float acc = dwb[c];
    #pragma unroll
    for (int ky = 0; ky < 7; ky++) {
        int yy = h + ky - 3;
        if (yy < 0 || yy > 127) continue;
        #pragma unroll
        for (int kx = 0; kx < 7; kx++) {
            int xx = wcol + kx - 3;
            if (xx < 0 || xx > 127) continue;
            acc += xp[yy*WW + xx] * w[ky*7 + kx];
        }
    }
    int oldc = 32 + c;
    int newc = (oldc < 64) ? (2*oldc) : (2*(oldc-64)+1);
    g_y[((size_t)b*DIM + newc)*HW + hw] = acc;
}

// ======================= BN1 + weight folding =======================
__global__ void k_bn1_part() {
    int bc = blockIdx.x;
    const float* p = g_y + (size_t)bc*HW;
    float s = 0.f, q = 0.f;
    for (int i = threadIdx.x; i < HW; i += 256) { float v = p[i]; s += v; q += v*v; }
    __shared__ float ss[256], qs[256];
    ss[threadIdx.x] = s; qs[threadIdx.x] = q;
    __syncthreads();
    for (int st = 128; st > 0; st >>= 1) {
        if (threadIdx.x < st) { ss[threadIdx.x] += ss[threadIdx.x+st]; qs[threadIdx.x] += qs[threadIdx.x+st]; }
        __syncthreads();
    }
    if (threadIdx.x == 0) { g_bn1_sum[bc] = ss[0]; g_bn1_sq[bc] = qs[0]; }
}
__global__ void k_bn1_final(const float* __restrict__ g, const float* __restrict__ be) {
    int c = threadIdx.x;
    float s = 0.f, q = 0.f;
    #pragma unroll
    for (int b = 0; b < BATCH; b++) { s += g_bn1_sum[b*DIM + c]; q += g_bn1_sq[b*DIM + c]; }
    float mean = s * (1.0f/NP);
    float var  = q * (1.0f/NP) - mean*mean;
    float rstd = rsqrtf(var + 1e-5f);
    float sc = g[c] * rstd;
    g_scale1[c] = sc;
    g_shift1[c] = be[c] - mean * sc;
}
__global__ void k_fold_w1(const float* __restrict__ w1, const float* __restrict__ b1) {
    int n = threadIdx.x;  // 512 threads
    float bf = b1[n];
    for (int k = 0; k < DIM; k++) {
        float w = w1[k*HID + n];
        g_w1f[k*HID + n] = w * g_scale1[k];
        bf += g_shift1[k] * w;
    }
    g_b1f[n] = bf;
}

// ======================= tf32 mma.sync GEMMs =======================
// GEMM1: [NP,128] x [128,512] (+b1f, gelu) -> g_t transposed [HID][NP]
__global__ __launch_bounds__(256) void k_gemm1() {
    extern __shared__ uint32_t sm4[];
    uint32_t* As = sm4;                 // [32][KSTR]
    uint32_t* Bs = sm4 + 32*KSTR;
    float* ts = (float*)sm4;            // epilogue transpose [128][TSTR]
    int tid = threadIdx.x;
    int lane = tid & 31, wid = tid >> 5;
    int g = lane >> 2, t = lane & 3;
    int warp_m = wid >> 2, warp_n = wid & 3;
    int p0 = blockIdx.y * 128, n0 = blockIdx.x * 128;
    int cb = (p0 >> 14) * DIM;
    int hw0 = p0 & (HW-1);

    float acc[4][4][4] = {};
    for (int kt = 0; kt < DIM; kt += 32) {
        #pragma unroll
        for (int l = 0; l < 4; l++) {
            int i = tid + l*256;
            int k = i >> 5, p4 = (i & 31) << 2;
            float4 v = *(const float4*)(g_y + (size_t)(cb + kt + k)*HW + hw0 + p4);
            uint32_t* d = As + k*KSTR + p4;
            d[0] = f2tf32(v.x); d[1] = f2tf32(v.y); d[2] = f2tf32(v.z); d[3] = f2tf32(v.w);
        }
        #pragma unroll
        for (int l = 0; l < 4; l++) {
            int i = tid + l*256;
            int k = i >> 5, n4 = (i & 31) << 2;
            float4 v = *(const float4*)(g_w1f + (size_t)(kt + k)*HID + n0 + n4);
            uint32_t* d = Bs + k*KSTR + n4;
            d[0] = f2tf32(v.x); d[1] = f2tf32(v.y); d[2] = f2tf32(v.z); d[3] = f2tf32(v.w);
        }
        __syncthreads();
        #pragma unroll
        for (int ks = 0; ks < 4; ks++) {
            uint32_t a[4][4], b[4][2];
            #pragma unroll
            for (int mi = 0; mi < 4; mi++) {
                int row = warp_m*64 + mi*16 + g;
                a[mi][0] = As[(ks*8 + t    )*KSTR + row];
                a[mi][1] = As[(ks*8 + t    )*KSTR + row + 8];
                a[mi][2] = As[(ks*8 + t + 4)*KSTR + row];
                a[mi][3] = As[(ks*8 + t + 4)*KSTR + row + 8];
            }
            #pragma unroll
            for (int nt = 0; nt < 4; nt++) {
                int col = warp_n*32 + nt*8 + g;
                b[nt][0] = Bs[(ks*8 + t    )*KSTR + col];
                b[nt][1] = Bs[(ks*8 + t + 4)*KSTR + col];
            }
            #pragma unroll
            for (int mi = 0; mi < 4; mi++)
                #pragma unroll
                for (int nt = 0; nt < 4; nt++)
                    mma_tf32(acc[mi][nt], a[mi], b[nt]);
        }
        __syncthreads();
    }
    // epilogue: bias + gelu, smem transpose, coalesced transposed store
    #pragma unroll
    for (int mi = 0; mi < 4; mi++) {
        int row = warp_m*64 + mi*16 + g;
        #pragma unroll
        for (int nt = 0; nt < 4; nt++) {
            int col = warp_n*32 + nt*8 + 2*t;
            float b0v = g_b1f[n0 + col], b1v = g_b1f[n0 + col + 1];
            ts[row*TSTR + col]       = gelu_exact(acc[mi][nt][0] + b0v);
            ts[row*TSTR + col + 1]   = gelu_exact(acc[mi][nt][1] + b1v);
            ts[(row+8)*TSTR + col]   = gelu_exact(acc[mi][nt][2] + b0v);
            ts[(row+8)*TSTR + col+1] = gelu_exact(acc[mi][nt][3] + b1v);
        }
    }
    __syncthreads();
    #pragma unroll
    for (int l = 0; l < 64; l++) {
        int i = tid + l*256;
        int n = i >> 7, p = i & 127;
        g_t[(size_t)(n0 + n)*NP + p0 + p] = ts[p*TSTR + n];
    }
}

// GEMM2: [NP,512] x [512,128] (+b2) -> g_c2 transposed [DIM][NP]
__global__ __launch_bounds__(256) void k_gemm2(const float* __restrict__ w2,
                                               const float* __restrict__ b2) {
    extern __shared__ uint32_t sm4[];
    uint32_t* As = sm4;
    uint32_t* Bs = sm4 + 32*KSTR;
    float* ts = (float*)sm4;
    int tid = threadIdx.x;
    int lane = tid & 31, wid = tid >> 5;
    int g = lane >> 2, t = lane & 3;
    int warp_m = wid >> 2, warp_n = wid & 3;
    int p0 = blockIdx.x * 128;

    float acc[4][4][4] = {};
    for (int kt = 0; kt < HID; kt += 32) {
        #pragma unroll
        for (int l = 0; l < 4; l++) {
            int i = tid + l*256;
            int k = i >> 5, p4 = (i & 31) << 2;
            float4 v = *(const float4*)(g_t + (size_t)(kt + k)*NP + p0 + p4);
            uint32_t* d = As + k*KSTR + p4;
            d[0] = f2tf32(v.x); d[1] = f2tf32(v.y); d[2] = f2tf32(v.z); d[3] = f2tf32(v.w);
        }
        #pragma unroll
        for (int l = 0; l < 4; l++) {
            int i = tid + l*256;
            int k = i >> 5, n4 = (i & 31) << 2;
            float4 v = *(const float4*)(w2 + (size_t)(kt + k)*DIM + n4);
            uint32_t* d = Bs + k*KSTR + n4;
            d[0] = f2tf32(v.x); d[1] = f2tf32(v.y); d[2] = f2tf32(v.z); d[3] = f2tf32(v.w);
        }
        __syncthreads();
        #pragma unroll
        for (int ks = 0; ks < 4; ks++) {
            uint32_t a[4][4], b[4][2];
            #pragma unroll
            for (int mi = 0; mi < 4; mi++) {
                int row = warp_m*64 + mi*16 + g;
                a[mi][0] = As[(ks*8 + t    )*KSTR + row];
                a[mi][1] = As[(ks*8 + t    )*KSTR + row + 8];
                a[mi][2] = As[(ks*8 + t + 4)*KSTR + row];
                a[mi][3] = As[(ks*8 + t + 4)*KSTR + row + 8];
            }
            #pragma unroll
            for (int nt = 0; nt < 4; nt++) {
                int col = warp_n*32 + nt*8 + g;
                b[nt][0] = Bs[(ks*8 + t    )*KSTR + col];
                b[nt][1] = Bs[(ks*8 + t + 4)*KSTR + col];
            }
            #pragma unroll
            for (int mi = 0; mi < 4; mi++)
                #pragma unroll
                for (int nt = 0; nt < 4; nt++)
                    mma_tf32(acc[mi][nt], a[mi], b[nt]);
        }
        __syncthreads();
    }
    #pragma unroll
    for (int mi = 0; mi < 4; mi++) {
        int row = warp_m*64 + mi*16 + g;
        #pragma unroll
        for (int nt = 0; nt < 4; nt++) {
            int col = warp_n*32 + nt*8 + 2*t;
            float b0v = b2[col], b1v = b2[col + 1];
            ts[row*TSTR + col]       = acc[mi][nt][0] + b0v;
            ts[row*TSTR + col + 1]   = acc[mi][nt][1] + b1v;
            ts[(row+8)*TSTR + col]   = acc[mi][nt][2] + b0v;
            ts[(row+8)*TSTR + col+1] = acc[mi][nt][3] + b1v;
        }
    }
    __syncthreads();
    #pragma unroll
    for (int l = 0; l < 64; l++) {
        int i = tid + l*256;
        int n = i >> 7, p = i & 127;
        g_c2[(size_t)n*NP + p0 + p] = ts[p*TSTR + n];
    }
}

// ======================= BN2 + final =======================
__global__ void k_bn2_part() {
    int c = blockIdx.x, seg = blockIdx.y;
    const float* p = g_c2 + (size_t)c*NP + seg*8192;
    float s = 0.f, q = 0.f;
    for (int i = threadIdx.x; i < 8192; i += 256) { float v = p[i]; s += v; q += v*v; }
    __shared__ float ss[256], qs[256];
    ss[threadIdx.x] = s; qs[threadIdx.x] = q;
    __syncthreads();
    for (int st = 128; st > 0; st >>= 1) {
        if (threadIdx.x < st) { ss[threadIdx.x] += ss[threadIdx.x+st]; qs[threadIdx.x] += qs[threadIdx.x+st]; }
        __syncthreads();
    }
    if (threadIdx.x == 0) { g_bn2_sum[seg*DIM + c] = ss[0]; g_bn2_sq[seg*DIM + c] = qs[0]; }
}
__global__ void k_bn2_final(const float* __restrict__ g, const float* __restrict__ be) {
    int c = threadIdx.x;
    float s = 0.f, q = 0.f;
    #pragma unroll
    for (int i = 0; i < 8; i++) { s += g_bn2_sum[i*DIM + c]; q += g_bn2_sq[i*DIM + c]; }
    float mean = s * (1.0f/NP);
    float var  = q * (1.0f/NP) - mean*mean;
    float rstd = rsqrtf(var + 1e-5f);
    float sc = g[c] * rstd;
    g_scale2[c] = sc;
    g_shift2[c] = be[c] - mean * sc;
}
__global__ void k_final(const float* __restrict__ x, float* __restrict__ out) {
    int i = blockIdx.x * 256 + threadIdx.x;
    int b = i >> 21;
    int c = (i >> 14) & 127;
    int hw = i & 16383;
    float v = g_c2[(size_t)c*NP + (b<<14) + hw] * g_scale2[c] + g_shift2[c];
    out[i] = gelu_exact(x[i] + v);
}

// ================================ launch ================================
extern "C" void kernel_launch(void* const* d_in, const int* in_sizes, int n_in,
                              void* d_out, int out_size) {
    const float* x        = (const float*)d_in[0];
    const float* offset_w = (const float*)d_in[1];
    const float* offset_b = (const float*)d_in[2];
    const float* deform_w = (const float*)d_in[3];
    const float* dw_w     = (const float*)d_in[4];
    const float* dw_b     = (const float*)d_in[5];
    const float* dw2_w    = (const float*)d_in[6];
    const float* dw2_b    = (const float*)d_in[7];
    const float* bn1_g    = (const float*)d_in[8];
    const float* bn1_b    = (const float*)d_in[9];
    const float* w1       = (const float*)d_in[10];
    const float* b1       = (const float*)d_in[11];
    const float* w2       = (const float*)d_in[12];
    const float* b2       = (const float*)d_in[13];
    const float* bn2_g    = (const float*)d_in[14];
    const float* bn2_b    = (const float*)d_in[15];
    float* out = (float*)d_out;

    static int smem_set = 0;
    const int GSMEM = 128*TSTR*4;   // 66560 bytes (>= 2*32*KSTR*4 = 34816)
    if (!smem_set) {
        cudaFuncSetAttribute(k_gemm1, cudaFuncAttributeMaxDynamicSharedMemorySize, GSMEM);
        cudaFuncSetAttribute(k_gemm2, cudaFuncAttributeMaxDynamicSharedMemorySize, GSMEM);
        smem_set = 1;
    }

    dim3 blk256(256);
    k_offset_v2<<<dim3(16, 3, BATCH), blk256>>>(x, offset_w, offset_b);
    k_deform   <<<dim3(HW/256, GC1, BATCH), blk256>>>(x, deform_w);
    k_dw7      <<<dim3(HW/256, GC2, BATCH), blk256>>>(x, dw_w, dw_b);
    k_dil3_v2  <<<dim3(16, 4, BATCH), blk256>>>(x, dw2_w, dw2_b);

    k_bn1_part <<<BATCH*DIM, blk256>>>();
    k_bn1_final<<<1, DIM>>>(bn1_g, bn1_b);
    k_fold_w1  <<<1, HID>>>(w1, b1);

    k_gemm1<<<dim3(HID/128, NP/128), 256, GSMEM>>>();
    k_gemm2<<<NP/128, 256, GSMEM>>>(w2, b2);

    k_bn2_part <<<dim3(DIM, 8), blk256>>>();
    k_bn2_final<<<1, DIM>>>(bn2_g, bn2_b);

    k_final<<<(size_t)NP*DIM/256, blk256>>>(x, out);
}

// round 4
// speedup vs baseline: 2.3430x; 1.1872x over previous
#include <cuda_runtime.h>
#include <cuda_bf16.h>
#include <math.h>
#include <stdint.h>

#define BATCH 4
#define DIM 128
#define HH 128
#define WW 128
#define HW (HH*WW)           // 16384
#define NP (BATCH*HW)        // 65536
#define HID 512
#define GC1 32
#define GC2 64
#define GC3 32

// ---------------- scratch ----------------
__device__ float g_off[BATCH*18*HW];
__device__ float g_y[BATCH*DIM*HW];            // shuffled concat, NCHW
__device__ float g_t[(size_t)HID*NP];          // GEMM1 out, TRANSPOSED [HID][NP]
__device__ float g_c2[(size_t)DIM*NP];         // GEMM2 out, TRANSPOSED [DIM][NP]
__device__ float g_w1f[DIM*HID];               // BN1-folded w1
__device__ float g_b1f[HID];
__device__ float g_bn1_sum[BATCH*DIM];
__device__ float g_bn1_sq [BATCH*DIM];
__device__ float g_scale1[DIM], g_shift1[DIM];
__device__ float g_bn2_sum[8*DIM];
__device__ float g_bn2_sq [8*DIM];
__device__ float g_scale2[DIM], g_shift2[DIM];

__device__ __forceinline__ float gelu_exact(float v) {
    return 0.5f * v * (1.0f + erff(v * 0.70710678118654752440f));
}
__device__ __forceinline__ uint32_t f2tf32(float f) {
    uint32_t r;
    asm("cvt.rna.tf32.f32 %0, %1;" : "=r"(r) : "f"(f));
    return r;
}
__device__ __forceinline__ void mma_tf32(float* c, const uint32_t* a, const uint32_t* b) {
    asm volatile("mma.sync.aligned.m16n8k8.row.col.f32.tf32.tf32.f32 "
        "{%0,%1,%2,%3}, {%4,%5,%6,%7}, {%8,%9}, {%0,%1,%2,%3};"
        : "+f"(c[0]), "+f"(c[1]), "+f"(c[2]), "+f"(c[3])
        : "r"(a[0]), "r"(a[1]), "r"(a[2]), "r"(a[3]), "r"(b[0]), "r"(b[1]));
}

#define KSTR 136   // smem row stride (floats): conflict-free frags + aligned STS.64
#define TSTR 130   // epilogue transpose stride

// ======================= conv kernels =======================
// All spatial convs: 32x16 tile, 256 threads, 2 pixels/thread.

// offset conv 3x3 pad1, 32->18, 6 oc per block.  grid (32, 3, 4)
__global__ __launch_bounds__(256) void k_offset_v3(const float* __restrict__ x,
                                                   const float* __restrict__ ow,
                                                   const float* __restrict__ ob) {
    __shared__ float s[4*18*34];   // 4 ic x (16+2) rows x (32+2) cols
    __shared__ float ws[6*4*9];
    int tid = threadIdx.x;
    int lx = tid & 31, lyq = tid >> 5;        // 8 row-groups
    int b = blockIdx.z;
    int oc0 = blockIdx.y * 6;
    int ty0 = (blockIdx.x >> 2) * 16, tx0 = (blockIdx.x & 3) * 32;
    float acc[6][2] = {};
    for (int icc = 0; icc < 8; icc++) {
        int ic0 = icc * 4;
        const float* xb = x + ((size_t)b*DIM + ic0)*HW;
        #pragma unroll 3
        for (int i = tid; i < 4*18*34; i += 256) {
            int icl = i / 612, e = i % 612;
            int sy = e / 34, sx = e % 34;
            int gy = ty0 + sy - 1, gx = tx0 + sx - 1;
            float v = 0.f;
            if (gy >= 0 && gy < 128 && gx >= 0 && gx < 128) v = xb[(size_t)icl*HW + gy*WW + gx];
            s[i] = v;
        }
        if (tid < 216) {
            int ocl = tid / 36, icl = (tid % 36) / 9, k = tid % 9;
            ws[tid] = ow[(oc0+ocl)*(GC1*9) + (ic0+icl)*9 + k];
        }
        __syncthreads();
        #pragma unroll
        for (int icl = 0; icl < 4; icl++) {
            #pragma unroll
            for (int q = 0; q < 2; q++) {
                int ly = lyq + q*8;
                const float* sp = s + icl*612 + ly*34 + lx;
                float t0 = sp[0],  t1 = sp[1],  t2 = sp[2];
                float t3 = sp[34], t4 = sp[35], t5 = sp[36];
                float t6 = sp[68], t7 = sp[69], t8 = sp[70];
                #pragma unroll
                for (int o = 0; o < 6; o++) {
                    const float* wp = ws + (o*4 + icl)*9;
                    acc[o][q] += t0*wp[0] + t1*wp[1] + t2*wp[2]
                               + t3*wp[3] + t4*wp[4] + t5*wp[5]
                               + t6*wp[6] + t7*wp[7] + t8*wp[8];
                }
            }
        }
        __syncthreads();
    }
    #pragma unroll
    for (int o = 0; o < 6; o++) {
        float bias = ob[oc0+o];
        #pragma unroll
        for (int q = 0; q < 2; q++) {
            int ly = lyq + q*8;
            g_off[((size_t)b*18 + oc0+o)*HW + (ty0+ly)*WW + tx0+lx] = acc[o][q] + bias;
        }
    }
}

// dilated 3x3 (d=2, pad=2), 32->32, 8 oc per block.  grid (32, 4, 4)
__global__ __launch_bounds__(256) void k_dil3_v3(const float* __restrict__ x,
                                                 const float* __restrict__ w2w,
                                                 const float* __restrict__ w2b) {
    __shared__ float s[4*20*36];   // 4 ic x (16+4) rows x (32+4) cols
    __shared__ float ws[8*4*9];
    int tid = threadIdx.x;
    int lx = tid & 31, lyq = tid >> 5;
    int b = blockIdx.z;
    int oc0 = blockIdx.y * 8;
    int ty0 = (blockIdx.x >> 2) * 16, tx0 = (blockIdx.x & 3) * 32;
    float acc[8][2] = {};
    for (int icc = 0; icc < 8; icc++) {
        int ic0 = icc * 4;
        const float* xb = x + ((size_t)b*DIM + 96 + ic0)*HW;
        #pragma unroll 3
        for (int i = tid; i < 4*20*36; i += 256) {
            int icl = i / 720, e = i % 720;
            int sy = e / 36, sx = e % 36;
            int gy = ty0 + sy - 2, gx = tx0 + sx - 2;
            float v = 0.f;
            if (gy >= 0 && gy < 128 && gx >= 0 && gx < 128) v = xb[(size_t)icl*HW + gy*WW + gx];
            s[i] = v;
        }
        #pragma unroll 2
        for (int i = tid; i < 288; i += 256) {
            int ocl = i / 36, icl = (i % 36) / 9, k = i % 9;
            ws[i] = w2w[(oc0+ocl)*(GC3*9) + (ic0+icl)*9 + k];
        }
        __syncthreads();
        #pragma unroll
        for (int icl = 0; icl < 4; icl++) {
            #pragma unroll
            for (int q = 0; q < 2; q++) {
                int ly = lyq + q*8;
                const float* sp = s + icl*720 + ly*36 + lx;
                float t0 = sp[0],   t1 = sp[2],   t2 = sp[4];
                float t3 = sp[72],  t4 = sp[74],  t5 = sp[76];
                float t6 = sp[144], t7 = sp[146], t8 = sp[148];
                #pragma unroll
                for (int o = 0; o < 8; o++) {
                    const float* wp = ws + (o*4 + icl)*9;
                    acc[o][q] += t0*wp[0] + t1*wp[1] + t2*wp[2]
                               + t3*wp[3] + t4*wp[4] + t5*wp[5]
                               + t6*wp[6] + t7*wp[7] + t8*wp[8];
                }
            }
        }
        __syncthreads();
    }
    #pragma unroll
    for (int o = 0; o < 8; o++) {
        float bias = w2b[oc0+o];
        int newc = 65 + 2*(oc0+o);
        #pragma unroll
        for (int q = 0; q < 2; q++) {
            int ly = lyq + q*8;
            g_y[((size_t)b*DIM + newc)*HW + (ty0+ly)*WW + tx0+lx] = acc[o][q] + bias;
        }
    }
}

// depthwise 7x7, smem-tiled.  grid (32, 64, 4)
__global__ __launch_bounds__(256) void k_dw7_v2(const float* __restrict__ x,
                                                const float* __restrict__ dww,
                                                const float* __restrict__ dwb) {
    __shared__ float s[22*38];     // (16+6) rows x (32+6) cols
    __shared__ float w[49];
    int tid = threadIdx.x;
    int lx = tid & 31, lyq = tid >> 5;
    int b = blockIdx.z;
    int c = blockIdx.y;   // 0..63
    int ty0 = (blockIdx.x >> 2) * 16, tx0 = (blockIdx.x & 3) * 32;
    const float* xp = x + ((size_t)b*DIM + 32 + c)*HW;
    #pragma unroll 4
    for (int i = tid; i < 22*38; i += 256) {
        int sy = i / 38, sx = i % 38;
        int gy = ty0 + sy - 3, gx = tx0 + sx - 3;
        float v = 0.f;
        if (gy >= 0 && gy < 128 && gx >= 0 && gx < 128) v = xp[gy*WW + gx];
        s[i] = v;
    }
    if (tid < 49) w[tid] = dww[c*49 + tid];
    __syncthreads();
    float bias = dwb[c];
    int oldc = 32 + c;
    int newc = (oldc < 64) ? (2*oldc) : (2*(oldc-64)+1);
    float* yp = g_y + ((size_t)b*DIM + newc)*HW;
    #pragma unroll
    for (int q = 0; q < 2; q++) {
        int ly = lyq + q*8;
        const float* sp = s + ly*38 + lx;
        float acc = bias;
        #pragma unroll
        for (int ky = 0; ky < 7; ky++)
            #pragma unroll
            for (int kx = 0; kx < 7; kx++)
                acc += sp[ky*38 + kx] * w[ky*7 + kx];
        yp[(ty0+ly)*WW + tx0+lx] = acc;
    }
}

// deformable depthwise (gather-bound; unchanged)
__global__ void k_deform(const float* __restrict__ x, const float* __restrict__ dfw) {
    int b = blockIdx.z;
    int c = blockIdx.y;
    int hw = blockIdx.x * 256 + threadIdx.x;
    __shared__ float wk[9];
    if (threadIdx.x < 9) wk[threadIdx.x] = dfw[c*9 + threadIdx.x];
    __syncthreads();
    int h = hw >> 7, wcol = hw & 127;
    const float* xp = x + ((size_t)b*DIM + c)*HW;
    const float* offb = g_off + (size_t)b*18*HW;
    float acc = 0.f;
    #pragma unroll
    for (int k = 0; k < 9; k++) {
        float dy = offb[(2*k  )*HW + hw];
        float dx = offb[(2*k+1)*HW + hw];
        float ys = (float)h - 1.0f + (float)(k/3) + dy;
        float xs = (float)wcol - 1.0f + (float)(k%3) + dx;
        float y0 = floorf(ys), x0 = floorf(xs);
        float sv = 0.f;
        #pragma unroll
        for (int dyb = 0; dyb < 2; dyb++)
            #pragma unroll
            for (int dxb = 0; dxb < 2; dxb++) {
                float yc = y0 + dyb, xc = x0 + dxb;
                float wt = (1.0f - fabsf(ys - yc)) * (1.0f - fabsf(xs - xc));
                if (yc >= 0.f && yc <= 127.f && xc >= 0.f && xc <= 127.f) {
                    sv += xp[(int)yc*WW + (int)xc] * wt;
                }
            }
        acc += sv * wk[k];
    }
    g_y[((size_t)b*DIM + 2*c)*HW + hw] = acc;
}

// ======================= BN1 + weight folding =======================
__global__ void k_bn1_part() {
    int bc = blockIdx.x;
    const float* p = g_y + (size_t)bc*HW;
    float s = 0.f, q = 0.f;
    for (int i = threadIdx.x; i < HW; i += 256) { float v = p[i]; s += v; q += v*v; }
    __shared__ float ss[256], qs[256];
    ss[threadIdx.x] = s; qs[threadIdx.x] = q;
    __syncthreads();
    for (int st = 128; st > 0; st >>= 1) {
        if (threadIdx.x < st) { ss[threadIdx.x] += ss[threadIdx.x+st]; qs[threadIdx.x] += qs[threadIdx.x+st]; }
        __syncthreads();
    }
    if (threadIdx.x == 0) { g_bn1_sum[bc] = ss[0]; g_bn1_sq[bc] = qs[0]; }
}
__global__ void k_bn1_final(const float* __restrict__ g, const float* __restrict__ be) {
    int c = threadIdx.x;
    float s = 0.f, q = 0.f;
    #pragma unroll
    for (int b = 0; b < BATCH; b++) { s += g_bn1_sum[b*DIM + c]; q += g_bn1_sq[b*DIM + c]; }
    float mean = s * (1.0f/NP);
    float var  = q * (1.0f/NP) - mean*mean;
    float rstd = rsqrtf(var + 1e-5f);
    float sc = g[c] * rstd;
    g_scale1[c] = sc;
    g_shift1[c] = be[c] - mean * sc;
}
__global__ void k_fold_w1(const float* __restrict__ w1, const float* __restrict__ b1) {
    int n = threadIdx.x;  // 512 threads
    float bf = b1[n];
    for (int k = 0; k < DIM; k++) {
        float w = w1[k*HID + n];
        g_w1f[k*HID + n] = w * g_scale1[k];
        bf += g_shift1[k] * w;
    }
    g_b1f[n] = bf;
}

// ======================= tf32 mma.sync GEMMs =======================
// GEMM1: [NP,128] x [128,512] (+b1f, gelu) -> g_t transposed [HID][NP]
__global__ __launch_bounds__(256) void k_gemm1() {
    extern __shared__ uint32_t sm4[];
    uint32_t* As = sm4;                 // [32][KSTR]
    uint32_t* Bs = sm4 + 32*KSTR;
    float* ts = (float*)sm4;            // epilogue transpose [128][TSTR]
    int tid = threadIdx.x;
    int lane = tid & 31, wid = tid >> 5;
    int g = lane >> 2, t = lane & 3;
    int warp_m = wid >> 2, warp_n = wid & 3;
    int p0 = blockIdx.y * 128, n0 = blockIdx.x * 128;
    int cb = (p0 >> 14) * DIM;
    int hw0 = p0 & (HW-1);

    int ka = tid >> 5, p4 = (tid & 31) << 2;   // per-thread A-tile slot
    float acc[4][4][4] = {};
    // initial fill (kt = 0)
    {
        #pragma unroll
        for (int l = 0; l < 4; l++) {
            int k = ka + l*8;
            float4 v = *(const float4*)(g_y + (size_t)(cb + k)*HW + hw0 + p4);
            uint32_t* d = As + k*KSTR + p4;
            d[0] = f2tf32(v.x); d[1] = f2tf32(v.y); d[2] = f2tf32(v.z); d[3] = f2tf32(v.w);
        }
        #pragma unroll
        for (int l = 0; l < 4; l++) {
            int k = ka + l*8;
            float4 v = *(const float4*)(g_w1f + (size_t)k*HID + n0 + p4);
            uint32_t* d = Bs + k*KSTR + p4;
            d[0] = f2tf32(v.x); d[1] = f2tf32(v.y); d[2] = f2tf32(v.z); d[3] = f2tf32(v.w);
        }
    }
    __syncthreads();
    for (int kc = 0; kc < 4; kc++) {
        float4 pa[4];
        if (kc < 3) {
            int kt = (kc+1)*32;
            #pragma unroll
            for (int l = 0; l < 4; l++)
                pa[l] = *(const float4*)(g_y + (size_t)(cb + kt + ka + l*8)*HW + hw0 + p4);
        }
        #pragma unroll
        for (int ks = 0; ks < 4; ks++) {
            uint32_t a[4][4], b[4][2];
            #pragma unroll
            for (int mi = 0; mi < 4; mi++) {
                int row = warp_m*64 + mi*16 + g;
                a[mi][0] = As[(ks*8 + t    )*KSTR + row];
                a[mi][1] = As[(ks*8 + t    )*KSTR + row + 8];
                a[mi][2] = As[(ks*8 + t + 4)*KSTR + row];
                a[mi][3] = As[(ks*8 + t + 4)*KSTR + row + 8];
            }
            #pragma unroll
            for (int nt = 0; nt < 4; nt++) {
                int col = warp_n*32 + nt*8 + g;
                b[nt][0] = Bs[(ks*8 + t    )*KSTR + col];
                b[nt][1] = Bs[(ks*8 + t + 4)*KSTR + col];
            }
            #pragma unroll
            for (int mi = 0; mi < 4; mi++)
                #pragma unroll
                for (int nt = 0; nt < 4; nt++)
                    mma_tf32(acc[mi][nt], a[mi], b[nt]);
        }
        __syncthreads();
        if (kc < 3) {
            int kt = (kc+1)*32;
            #pragma unroll
            for (int l = 0; l < 4; l++) {
                uint32_t* d = As + (ka + l*8)*KSTR + p4;
                d[0] = f2tf32(pa[l].x); d[1] = f2tf32(pa[l].y);
                d[2] = f2tf32(pa[l].z); d[3] = f2tf32(pa[l].w);
            }
            #pragma unroll
            for (int l = 0; l < 4; l++) {
                int k = ka + l*8;
                float4 v = *(const float4*)(g_w1f + (size_t)(kt + k)*HID + n0 + p4);
                uint32_t* d = Bs + k*KSTR + p4;
                d[0] = f2tf32(v.x); d[1] = f2tf32(v.y); d[2] = f2tf32(v.z); d[3] = f2tf32(v.w);
            }
            __syncthreads();
        }
    }
    // epilogue: bias + gelu, smem transpose, coalesced transposed store
    #pragma unroll
    for (int mi = 0; mi < 4; mi++) {
        int row = warp_m*64 + mi*16 + g;
        #pragma unroll
        for (int nt = 0; nt < 4; nt++) {
            int col = warp_n*32 + nt*8 + 2*t;
            float b0v = g_b1f[n0 + col], b1v = g_b1f[n0 + col + 1];
            ts[row*TSTR + col]       = gelu_exact(acc[mi][nt][0] + b0v);
            ts[row*TSTR + col + 1]   = gelu_exact(acc[mi][nt][1] + b1v);
            ts[(row+8)*TSTR + col]   = gelu_exact(acc[mi][nt][2] + b0v);
            ts[(row+8)*TSTR + col+1] = gelu_exact(acc[mi][nt][3] + b1v);
        }
    }
    __syncthreads();
    #pragma unroll
    for (int l = 0; l < 64; l++) {
        int i = tid + l*256;
        int n = i >> 7, p = i & 127;
        g_t[(size_t)(n0 + n)*NP + p0 + p] = ts[p*TSTR + n];
    }
}

// GEMM2: [NP,512] x [512,128] (+b2) -> g_c2 transposed [DIM][NP]
__global__ __launch_bounds__(256) void k_gemm2(const float* __restrict__ w2,
                                               const float* __restrict__ b2) {
    extern __shared__ uint32_t sm4[];
    uint32_t* As = sm4;
    uint32_t* Bs = sm4 + 32*KSTR;
    float* ts = (float*)sm4;
    int tid = threadIdx.x;
    int lane = tid & 31, wid = tid >> 5;
    int g = lane >> 2, t = lane & 3;
    int warp_m = wid >> 2, warp_n = wid & 3;
    int p0 = blockIdx.x * 128;

    int ka = tid >> 5, p4 = (tid & 31) << 2;
    float acc[4][4][4] = {};
    {
        #pragma unroll
        for (int l = 0; l < 4; l++) {
            int k = ka + l*8;
            float4 v = *(const float4*)(g_t + (size_t)k*NP + p0 + p4);
            uint32_t* d = As + k*KSTR + p4;
            d[0] = f2tf32(v.x); d[1] = f2tf32(v.y); d[2] = f2tf32(v.z); d[3] = f2tf32(v.w);
        }
        #pragma unroll
        for (int l = 0; l < 4; l++) {
            int k = ka + l*8;
            float4 v = *(const float4*)(w2 + (size_t)k*DIM + p4);
            uint32_t* d = Bs + k*KSTR + p4;
            d[0] = f2tf32(v.x); d[1] = f2tf32(v.y); d[2] = f2tf32(v.z); d[3] = f2tf32(v.w);
        }
    }
    __syncthreads();
    for (int kc = 0; kc < 16; kc++) {
        float4 pa[4];
        if (kc < 15) {
            int kt = (kc+1)*32;
            #pragma unroll
            for (int l = 0; l < 4; l++)
                pa[l] = *(const float4*)(g_t + (size_t)(kt + ka + l*8)*NP + p0 + p4);
        }
        #pragma unroll
        for (int ks = 0; ks < 4; ks++) {
            uint32_t a[4][4], b[4][2];
            #pragma unroll
            for (int mi = 0; mi < 4; mi++) {
                int row = warp_m*64 + mi*16 + g;
                a[mi][0] = As[(ks*8 + t    )*KSTR + row];
                a[mi][1] = As[(ks*8 + t    )*KSTR + row + 8];
                a[mi][2] = As[(ks*8 + t + 4)*KSTR + row];
                a[mi][3] = As[(ks*8 + t + 4)*KSTR + row + 8];
            }
            #pragma unroll
            for (int nt = 0; nt < 4; nt++) {
                int col = warp_n*32 + nt*8 + g;
                b[nt][0] = Bs[(ks*8 + t    )*KSTR + col];
                b[nt][1] = Bs[(ks*8 + t + 4)*KSTR + col];
            }
            #pragma unroll
            for (int mi = 0; mi < 4; mi++)
                #pragma unroll
                for (int nt = 0; nt < 4; nt++)
                    mma_tf32(acc[mi][nt], a[mi], b[nt]);
        }
        __syncthreads();
        if (kc < 15) {
            int kt = (kc+1)*32;
            #pragma unroll
            for (int l = 0; l < 4; l++) {
                uint32_t* d = As + (ka + l*8)*KSTR + p4;
                d[0] = f2tf32(pa[l].x); d[1] = f2tf32(pa[l].y);
                d[2] = f2tf32(pa[l].z); d[3] = f2tf32(pa[l].w);
            }
            #pragma unroll
            for (int l = 0; l < 4; l++) {
                int k = ka + l*8;
                float4 v = *(const float4*)(w2 + (size_t)(kt + k)*DIM + p4);
                uint32_t* d = Bs + k*KSTR + p4;
                d[0] = f2tf32(v.x); d[1] = f2tf32(v.y); d[2] = f2tf32(v.z); d[3] = f2tf32(v.w);
            }
            __syncthreads();
        }
    }
    #pragma unroll
    for (int mi = 0; mi < 4; mi++) {
        int row = warp_m*64 + mi*16 + g;
        #pragma unroll
        for (int nt = 0; nt < 4; nt++) {
            int col = warp_n*32 + nt*8 + 2*t;
            float b0v = b2[col], b1v = b2[col + 1];
            ts[row*TSTR + col]       = acc[mi][nt][0] + b0v;
            ts[row*TSTR + col + 1]   = acc[mi][nt][1] + b1v;
            ts[(row+8)*TSTR + col]   = acc[mi][nt][2] + b0v;
            ts[(row+8)*TSTR + col+1] = acc[mi][nt][3] + b1v;
        }
    }
    __syncthreads();
    #pragma unroll
    for (int l = 0; l < 64; l++) {
        int i = tid + l*256;
        int n = i >> 7, p = i & 127;
        g_c2[(size_t)n*NP + p0 + p] = ts[p*TSTR + n];
    }
}

// ======================= BN2 + final =======================
__global__ void k_bn2_part() {
    int c = blockIdx.x, seg = blockIdx.y;
    const float* p = g_c2 + (size_t)c*NP + seg*8192;
    float s = 0.f, q = 0.f;
    for (int i = threadIdx.x; i < 8192; i += 256) { float v = p[i]; s += v; q += v*v; }
    __shared__ float ss[256], qs[256];
    ss[threadIdx.x] = s; qs[threadIdx.x] = q;
    __syncthreads();
    for (int st = 128; st > 0; st >>= 1) {
        if (threadIdx.x < st) { ss[threadIdx.x] += ss[threadIdx.x+st]; qs[threadIdx.x] += qs[threadIdx.x+st]; }
        __syncthreads();
    }
    if (threadIdx.x == 0) { g_bn2_sum[seg*DIM + c] = ss[0]; g_bn2_sq[seg*DIM + c] = qs[0]; }
}
__global__ void k_bn2_final(const float* __restrict__ g, const float* __restrict__ be) {
    int c = threadIdx.x;
    float s = 0.f, q = 0.f;
    #pragma unroll
    for (int i = 0; i < 8; i++) { s += g_bn2_sum[i*DIM + c]; q += g_bn2_sq[i*DIM + c]; }
    float mean = s * (1.0f/NP);
    float var  = q * (1.0f/NP) - mean*mean;
    float rstd = rsqrtf(var + 1e-5f);
    float sc = g[c] * rstd;
    g_scale2[c] = sc;
    g_shift2[c] = be[c] - mean * sc;
}
__global__ void k_final(const float* __restrict__ x, float* __restrict__ out) {
    int i = blockIdx.x * 256 + threadIdx.x;
    int b = i >> 21;
    int c = (i >> 14) & 127;
    int hw = i & 16383;
    float v = g_c2[(size_t)c*NP + (b<<14) + hw] * g_scale2[c] + g_shift2[c];
    out[i] = gelu_exact(x[i] + v);
}

// ================================ launch ================================
extern "C" void kernel_launch(void* const* d_in, const int* in_sizes, int n_in,
                              void* d_out, int out_size) {
    const float* x        = (const float*)d_in[0];
    const float* offset_w = (const float*)d_in[1];
    const float* offset_b = (const float*)d_in[2];
    const float* deform_w = (const float*)d_in[3];
    const float* dw_w     = (const float*)d_in[4];
    const float* dw_b     = (const float*)d_in[5];
    const float* dw2_w    = (const float*)d_in[6];
    const float* dw2_b    = (const float*)d_in[7];
    const float* bn1_g    = (const float*)d_in[8];
    const float* bn1_b    = (const float*)d_in[9];
    const float* w1       = (const float*)d_in[10];
    const float* b1       = (const float*)d_in[11];
    const float* w2       = (const float*)d_in[12];
    const float* b2       = (const float*)d_in[13];
    const float* bn2_g    = (const float*)d_in[14];
    const float* bn2_b    = (const float*)d_in[15];
    float* out = (float*)d_out;

    static int smem_set = 0;
    const int GSMEM = 128*TSTR*4;   // 66560 bytes
    if (!smem_set) {
        cudaFuncSetAttribute(k_gemm1, cudaFuncAttributeMaxDynamicSharedMemorySize, GSMEM);
        cudaFuncSetAttribute(k_gemm2, cudaFuncAttributeMaxDynamicSharedMemorySize, GSMEM);
        smem_set = 1;
    }

    dim3 blk256(256);
    k_offset_v3<<<dim3(32, 3, BATCH), blk256>>>(x, offset_w, offset_b);
    k_deform   <<<dim3(HW/256, GC1, BATCH), blk256>>>(x, deform_w);
    k_dw7_v2   <<<dim3(32, GC2, BATCH), blk256>>>(x, dw_w, dw_b);
    k_dil3_v3  <<<dim3(32, 4, BATCH), blk256>>>(x, dw2_w, dw2_b);

    k_bn1_part <<<BATCH*DIM, blk256>>>();
    k_bn1_final<<<1, DIM>>>(bn1_g, bn1_b);
    k_fold_w1  <<<1, HID>>>(w1, b1);

    k_gemm1<<<dim3(HID/128, NP/128), 256, GSMEM>>>();
    k_gemm2<<<NP/128, 256, GSMEM>>>(w2, b2);

    k_bn2_part <<<dim3(DIM, 8), blk256>>>();
    k_bn2_final<<<1, DIM>>>(bn2_g, bn2_b);

    k_final<<<(size_t)NP*DIM/256, blk256>>>(x, out);
}

// round 5
// speedup vs baseline: 2.6520x; 1.1319x over previous
#include <cuda_runtime.h>
#include <cuda_bf16.h>
#include <math.h>
#include <stdint.h>

#define BATCH 4
#define DIM 128
#define HH 128
#define WW 128
#define HW (HH*WW)           // 16384
#define NP (BATCH*HW)        // 65536
#define HID 512
#define GC1 32
#define GC2 64
#define GC3 32

// ---------------- scratch ----------------
__device__ float g_off[BATCH*18*HW];
__device__ float g_y[BATCH*DIM*HW];            // shuffled concat, NCHW
__device__ float g_t[(size_t)HID*NP];          // GEMM1 out, TRANSPOSED [HID][NP]
__device__ float g_c2[(size_t)DIM*NP];         // GEMM2 out, TRANSPOSED [DIM][NP]
__device__ float g_w1f[DIM*HID];               // BN1-folded w1
__device__ float g_b1f[HID];
__device__ float g_bn1_sum[BATCH*DIM];
__device__ float g_bn1_sq [BATCH*DIM];
__device__ float g_scale1[DIM], g_shift1[DIM];
__device__ float g_bn2_sum[8*DIM];
__device__ float g_bn2_sq [8*DIM];
__device__ float g_scale2[DIM], g_shift2[DIM];

__device__ __forceinline__ float gelu_exact(float v) {
    return 0.5f * v * (1.0f + erff(v * 0.70710678118654752440f));
}
__device__ __forceinline__ uint32_t f2tf32(float f) {
    uint32_t r;
    asm("cvt.rna.tf32.f32 %0, %1;" : "=r"(r) : "f"(f));
    return r;
}
__device__ __forceinline__ void mma_tf32(float* c, const uint32_t* a, const uint32_t* b) {
    asm volatile("mma.sync.aligned.m16n8k8.row.col.f32.tf32.tf32.f32 "
        "{%0,%1,%2,%3}, {%4,%5,%6,%7}, {%8,%9}, {%0,%1,%2,%3};"
        : "+f"(c[0]), "+f"(c[1]), "+f"(c[2]), "+f"(c[3])
        : "r"(a[0]), "r"(a[1]), "r"(a[2]), "r"(a[3]), "r"(b[0]), "r"(b[1]));
}

#define KSTR 136   // GEMM smem row stride
#define TSTR 130   // epilogue transpose stride

// ======================= implicit-GEMM tensor conv =======================
// One block per (output row y, batch b). K = 9 taps * 32 ic = 288, M = 128 px, N = 32 oc (padded).
// MODE 0: write to g_off (oc < 18).  MODE 1: write to g_y at channel 65+2*oc.
#define ASTR 136   // A smem col stride (per k-row), 136 % 32 == 8 -> conflict-free
#define BSTR 40    // B smem n stride, 40 % 32 == 8 -> conflict-free
#define CONV_SMEM ((96*ASTR + 288*BSTR)*4)   // 98304 bytes

template<int NOC, int D, int CBASE, int MODE>
__global__ __launch_bounds__(256) void k_conv_mma(const float* __restrict__ x,
                                                  const float* __restrict__ w,   // [NOC][32][3][3]
                                                  const float* __restrict__ bias,
                                                  float* __restrict__ outp) {
    extern __shared__ uint32_t cs[];
    uint32_t* As = cs;               // [96][ASTR]  rows: ky*32+ic, col: gx + D
    uint32_t* Bs = cs + 96*ASTR;     // [288][BSTR] rows: tap*32+ic, col: oc
    int tid = threadIdx.x;
    int lane = tid & 31, wid = tid >> 5;
    int g = lane >> 2, t = lane & 3;
    int warp_m = wid >> 1, warp_n = wid & 1;
    int y = blockIdx.x, b = blockIdx.y;

    // fill A: 3 input rows (y-D, y, y+D) x 32 ic x cols [-D .. ) zero-padded
    for (int i = tid; i < 96*ASTR; i += 256) {
        int r = i / ASTR, c = i - r*ASTR;
        int ky = r >> 5, ic = r & 31;
        int ry = y + (ky - 1)*D;
        int gx = c - D;
        float v = 0.f;
        if (ry >= 0 && ry < 128 && gx >= 0 && gx < 128)
            v = x[(((size_t)b*DIM + CBASE + ic) << 14) + (ry << 7) + gx];
        As[i] = f2tf32(v);
    }
    // fill B: weights, zero-padded to 32 oc
    for (int i = tid; i < 288*32; i += 256) {
        int k = i >> 5, oc = i & 31;
        int tap = k >> 5, ic = k & 31;
        float v = (oc < NOC) ? w[(oc*32 + ic)*9 + tap] : 0.f;
        Bs[k*BSTR + oc] = f2tf32(v);
    }
    __syncthreads();

    float acc[2][2][4] = {};
    int mbase = warp_m*32 + g;
    int nbase = warp_n*16 + g;
    #pragma unroll
    for (int tap = 0; tap < 9; tap++) {
        const int ky = tap / 3, kx = tap % 3;
        #pragma unroll
        for (int k8 = 0; k8 < 4; k8++) {
            int ar = ky*32 + k8*8 + t;
            int bk = tap*32 + k8*8 + t;
            uint32_t a[2][4], bb[2][2];
            #pragma unroll
            for (int mi = 0; mi < 2; mi++) {
                int col = mbase + mi*16 + kx*D;
                a[mi][0] = As[ar*ASTR + col];
                a[mi][1] = As[ar*ASTR + col + 8];
                a[mi][2] = As[(ar + 4)*ASTR + col];
                a[mi][3] = As[(ar + 4)*ASTR + col + 8];
            }
            #pragma unroll
            for (int nt = 0; nt < 2; nt++) {
                bb[nt][0] = Bs[bk*BSTR + nbase + nt*8];
                bb[nt][1] = Bs[(bk + 4)*BSTR + nbase + nt*8];
            }
            #pragma unroll
            for (int mi = 0; mi < 2; mi++)
                #pragma unroll
                for (int nt = 0; nt < 2; nt++)
                    mma_tf32(acc[mi][nt], a[mi], bb[nt]);
        }
    }
    // epilogue: direct global store
    #pragma unroll
    for (int mi = 0; mi < 2; mi++) {
        #pragma unroll
        for (int nt = 0; nt < 2; nt++) {
            int col = warp_n*16 + nt*8 + 2*t;
            #pragma unroll
            for (int cc = 0; cc < 2; cc++) {
                int oc = col + cc;
                if (oc >= NOC) continue;
                float bv = bias[oc];
                int px0 = warp_m*32 + mi*16 + g;
                size_t base;
                if (MODE == 0) base = (((size_t)b*18 + oc) << 14) + (y << 7);
                else           base = (((size_t)b*DIM + 65 + 2*oc) << 14) + (y << 7);
                outp[base + px0]     = acc[mi][nt][cc]     + bv;
                outp[base + px0 + 8] = acc[mi][nt][cc + 2] + bv;
            }
        }
    }
}

// ======================= other conv kernels =======================

// depthwise 7x7, smem-tiled.  grid (32, 64, 4)
__global__ __launch_bounds__(256) void k_dw7_v2(const float* __restrict__ x,
                                                const float* __restrict__ dww,
                                                const float* __restrict__ dwb) {
    __shared__ float s[22*38];
    __shared__ float w[49];
    int tid = threadIdx.x;
    int lx = tid & 31, lyq = tid >> 5;
    int b = blockIdx.z;
    int c = blockIdx.y;
    int ty0 = (blockIdx.x >> 2) * 16, tx0 = (blockIdx.x & 3) * 32;
    const float* xp = x + ((size_t)b*DIM + 32 + c)*HW;
    #pragma unroll 4
    for (int i = tid; i < 22*38; i += 256) {
        int sy = i / 38, sx = i % 38;
        int gy = ty0 + sy - 3, gx = tx0 + sx - 3;
        float v = 0.f;
        if (gy >= 0 && gy < 128 && gx >= 0 && gx < 128) v = xp[gy*WW + gx];
        s[i] = v;
    }
    if (tid < 49) w[tid] = dww[c*49 + tid];
    __syncthreads();
    float bias = dwb[c];
    int oldc = 32 + c;
    int newc = (oldc < 64) ? (2*oldc) : (2*(oldc-64)+1);
    float* yp = g_y + ((size_t)b*DIM + newc)*HW;
    #pragma unroll
    for (int q = 0; q < 2; q++) {
        int ly = lyq + q*8;
        const float* sp = s + ly*38 + lx;
        float acc = bias;
        #pragma unroll
        for (int ky = 0; ky < 7; ky++)
            #pragma unroll
            for (int kx = 0; kx < 7; kx++)
                acc += sp[ky*38 + kx] * w[ky*7 + kx];
        yp[(ty0+ly)*WW + tx0+lx] = acc;
    }
}

// deformable depthwise v2: per-pixel tap data computed once, reused over 8 channels.
// grid (64, 4, 4): (hw chunk, c-group, batch)
__global__ __launch_bounds__(256) void k_deform_v2(const float* __restrict__ x,
                                                   const float* __restrict__ dfw) {
    int tid = threadIdx.x;
    int b = blockIdx.z;
    int c0 = blockIdx.y * 8;
    int hw = blockIdx.x * 256 + tid;
    int h = hw >> 7, wc = hw & 127;
    const float* offb = g_off + (size_t)b*18*HW + hw;

    float wq0[9], wq1[9], wq2[9], wq3[9];
    int i00[9], i01[9], i10[9], i11[9];
    #pragma unroll
    for (int k = 0; k < 9; k++) {
        float dy = offb[(2*k  )*HW];
        float dx = offb[(2*k+1)*HW];
        float ys = (float)h - 1.0f + (float)(k/3) + dy;
        float xs = (float)wc - 1.0f + (float)(k%3) + dx;
        float y0 = floorf(ys), x0 = floorf(xs);
        float fy = ys - y0, fx = xs - x0;
        float vy0 = (y0 >= 0.f && y0 <= 127.f) ? 1.f : 0.f;
        float vy1 = (y0 >= -1.f && y0 <= 126.f) ? 1.f : 0.f;
        float vx0 = (x0 >= 0.f && x0 <= 127.f) ? 1.f : 0.f;
        float vx1 = (x0 >= -1.f && x0 <= 126.f) ? 1.f : 0.f;
        wq0[k] = (1.f-fy)*(1.f-fx) * vy0*vx0;
        wq1[k] = (1.f-fy)*fx       * vy0*vx1;
        wq2[k] = fy*(1.f-fx)       * vy1*vx0;
        wq3[k] = fy*fx             * vy1*vx1;
        int yi0 = min(max((int)y0, 0), 127);
        int yi1 = min(max((int)y0 + 1, 0), 127);
        int xi0 = min(max((int)x0, 0), 127);
        int xi1 = min(max((int)x0 + 1, 0), 127);
        i00[k] = yi0*128 + xi0;
        i01[k] = yi0*128 + xi1;
        i10[k] = yi1*128 + xi0;
        i11[k] = yi1*128 + xi1;
    }
    #pragma unroll
    for (int cl = 0; cl < 8; cl++) {
        int c = c0 + cl;
        const float* xp = x + (((size_t)b*DIM + c) << 14);
        const float* wk = dfw + c*9;
        float acc = 0.f;
        #pragma unroll
        for (int k = 0; k < 9; k++) {
            float sv = wq0[k]*xp[i00[k]] + wq1[k]*xp[i01[k]]
                     + wq2[k]*xp[i10[k]] + wq3[k]*xp[i11[k]];
            acc += sv * wk[k];
        }
        g_y[(((size_t)b*DIM + 2*c) << 14) + hw] = acc;
    }
}

// ======================= BN1 + weight folding =======================
__global__ void k_bn1_part() {
    int bc = blockIdx.x;
    const float* p = g_y + (size_t)bc*HW;
    float s = 0.f, q = 0.f;
    for (int i = threadIdx.x; i < HW; i += 256) { float v = p[i]; s += v; q += v*v; }
    __shared__ float ss[256], qs[256];
    ss[threadIdx.x] = s; qs[threadIdx.x] = q;
    __syncthreads();
    for (int st = 128; st > 0; st >>= 1) {
        if (threadIdx.x < st) { ss[threadIdx.x] += ss[threadIdx.x+st]; qs[threadIdx.x] += qs[threadIdx.x+st]; }
        __syncthreads();
    }
    if (threadIdx.x == 0) { g_bn1_sum[bc] = ss[0]; g_bn1_sq[bc] = qs[0]; }
}
__global__ void k_bn1_final(const float* __restrict__ g, const float* __restrict__ be) {
    int c = threadIdx.x;
    float s = 0.f, q = 0.f;
    #pragma unroll
    for (int b = 0; b < BATCH; b++) { s += g_bn1_sum[b*DIM + c]; q += g_bn1_sq[b*DIM + c]; }
    float mean = s * (1.0f/NP);
    float var  = q * (1.0f/NP) - mean*mean;
    float rstd = rsqrtf(var + 1e-5f);
    float sc = g[c] * rstd;
    g_scale1[c] = sc;
    g_shift1[c] = be[c] - mean * sc;
}
__global__ void k_fold_w1(const float* __restrict__ w1, const float* __restrict__ b1) {
    int n = threadIdx.x;
    float bf = b1[n];
    for (int k = 0; k < DIM; k++) {
        float w = w1[k*HID + n];
        g_w1f[k*HID + n] = w * g_scale1[k];
        bf += g_shift1[k] * w;
    }
    g_b1f[n] = bf;
}

// ======================= tf32 mma.sync GEMMs =======================
__global__ __launch_bounds__(256) void k_gemm1() {
    extern __shared__ uint32_t sm4[];
    uint32_t* As = sm4;
    uint32_t* Bs = sm4 + 32*KSTR;
    float* ts = (float*)sm4;
    int tid = threadIdx.x;
    int lane = tid & 31, wid = tid >> 5;
    int g = lane >> 2, t = lane & 3;
    int warp_m = wid >> 2, warp_n = wid & 3;
    int p0 = blockIdx.y * 128, n0 = blockIdx.x * 128;
    int cb = (p0 >> 14) * DIM;
    int hw0 = p0 & (HW-1);

    int ka = tid >> 5, p4 = (tid & 31) << 2;
    float acc[4][4][4] = {};
    {
        #pragma unroll
        for (int l = 0; l < 4; l++) {
            int k = ka + l*8;
            float4 v = *(const float4*)(g_y + (size_t)(cb + k)*HW + hw0 + p4);
            uint32_t* d = As + k*KSTR + p4;
            d[0] = f2tf32(v.x); d[1] = f2tf32(v.y); d[2] = f2tf32(v.z); d[3] = f2tf32(v.w);
        }
        #pragma unroll
        for (int l = 0; l < 4; l++) {
            int k = ka + l*8;
            float4 v = *(const float4*)(g_w1f + (size_t)k*HID + n0 + p4);
            uint32_t* d = Bs + k*KSTR + p4;
            d[0] = f2tf32(v.x); d[1] = f2tf32(v.y); d[2] = f2tf32(v.z); d[3] = f2tf32(v.w);
        }
    }
    __syncthreads();
    for (int kc = 0; kc < 4; kc++) {
        float4 pa[4];
        if (kc < 3) {
            int kt = (kc+1)*32;
            #pragma unroll
            for (int l = 0; l < 4; l++)
                pa[l] = *(const float4*)(g_y + (size_t)(cb + kt + ka + l*8)*HW + hw0 + p4);
        }
        #pragma unroll
        for (int ks = 0; ks < 4; ks++) {
            uint32_t a[4][4], b[4][2];
            #pragma unroll
            for (int mi = 0; mi < 4; mi++) {
                int row = warp_m*64 + mi*16 + g;
                a[mi][0] = As[(ks*8 + t    )*KSTR + row];
                a[mi][1] = As[(ks*8 + t    )*KSTR + row + 8];
                a[mi][2] = As[(ks*8 + t + 4)*KSTR + row];
                a[mi][3] = As[(ks*8 + t + 4)*KSTR + row + 8];
            }
            #pragma unroll
            for (int nt = 0; nt < 4; nt++) {
                int col = warp_n*32 + nt*8 + g;
                b[nt][0] = Bs[(ks*8 + t    )*KSTR + col];
                b[nt][1] = Bs[(ks*8 + t + 4)*KSTR + col];
            }
            #pragma unroll
            for (int mi = 0; mi < 4; mi++)
                #pragma unroll
                for (int nt = 0; nt < 4; nt++)
                    mma_tf32(acc[mi][nt], a[mi], b[nt]);
        }
        __syncthreads();
        if (kc < 3) {
            int kt = (kc+1)*32;
            #pragma unroll
            for (int l = 0; l < 4; l++) {
                uint32_t* d = As + (ka + l*8)*KSTR + p4;
                d[0] = f2tf32(pa[l].x); d[1] = f2tf32(pa[l].y);
                d[2] = f2tf32(pa[l].z); d[3] = f2tf32(pa[l].w);
            }
            #pragma unroll
            for (int l = 0; l < 4; l++) {
                int k = ka + l*8;
                float4 v = *(const float4*)(g_w1f + (size_t)(kt + k)*HID + n0 + p4);
                uint32_t* d = Bs + k*KSTR + p4;
                d[0] = f2tf32(v.x); d[1] = f2tf32(v.y); d[2] = f2tf32(v.z); d[3] = f2tf32(v.w);
            }
            __syncthreads();
        }
    }
    #pragma unroll
    for (int mi = 0; mi < 4; mi++) {
        int row = warp_m*64 + mi*16 + g;
        #pragma unroll
        for (int nt = 0; nt < 4; nt++) {
            int col = warp_n*32 + nt*8 + 2*t;
            float b0v = g_b1f[n0 + col], b1v = g_b1f[n0 + col + 1];
            ts[row*TSTR + col]       = gelu_exact(acc[mi][nt][0] + b0v);
            ts[row*TSTR + col + 1]   = gelu_exact(acc[mi][nt][1] + b1v);
            ts[(row+8)*TSTR + col]   = gelu_exact(acc[mi][nt][2] + b0v);
            ts[(row+8)*TSTR + col+1] = gelu_exact(acc[mi][nt][3] + b1v);
        }
    }
    __syncthreads();
    #pragma unroll
    for (int l = 0; l < 64; l++) {
        int i = tid + l*256;
        int n = i >> 7, p = i & 127;
        g_t[(size_t)(n0 + n)*NP + p0 + p] = ts[p*TSTR + n];
    }
}

__global__ __launch_bounds__(256) void k_gemm2(const float* __restrict__ w2,
                                               const float* __restrict__ b2) {
    extern __shared__ uint32_t sm4[];
    uint32_t* As = sm4;
    uint32_t* Bs = sm4 + 32*KSTR;
    float* ts = (float*)sm4;
    int tid = threadIdx.x;
    int lane = tid & 31, wid = tid >> 5;
    int g = lane >> 2, t = lane & 3;
    int warp_m = wid >> 2, warp_n = wid & 3;
    int p0 = blockIdx.x * 128;

    int ka = tid >> 5, p4 = (tid & 31) << 2;
    float acc[4][4][4] = {};
    {
        #pragma unroll
        for (int l = 0; l < 4; l++) {
            int k = ka + l*8;
            float4 v = *(const float4*)(g_t + (size_t)k*NP + p0 + p4);
            uint32_t* d = As + k*KSTR + p4;
            d[0] = f2tf32(v.x); d[1] = f2tf32(v.y); d[2] = f2tf32(v.z); d[3] = f2tf32(v.w);
        }
        #pragma unroll
        for (int l = 0; l < 4; l++) {
            int k = ka + l*8;
            float4 v = *(const float4*)(w2 + (size_t)k*DIM + p4);
            uint32_t* d = Bs + k*KSTR + p4;
            d[0] = f2tf32(v.x); d[1] = f2tf32(v.y); d[2] = f2tf32(v.z); d[3] = f2tf32(v.w);
        }
    }
    __syncthreads();
    for (int kc = 0; kc < 16; kc++) {
        float4 pa[4];
        if (kc < 15) {
            int kt = (kc+1)*32;
            #pragma unroll
            for (int l = 0; l < 4; l++)
                pa[l] = *(const float4*)(g_t + (size_t)(kt + ka + l*8)*NP + p0 + p4);
        }
        #pragma unroll
        for (int ks = 0; ks < 4; ks++) {
            uint32_t a[4][4], b[4][2];
            #pragma unroll
            for (int mi = 0; mi < 4; mi++) {
                int row = warp_m*64 + mi*16 + g;
                a[mi][0] = As[(ks*8 + t    )*KSTR + row];
                a[mi][1] = As[(ks*8 + t    )*KSTR + row + 8];
                a[mi][2] = As[(ks*8 + t + 4)*KSTR + row];
                a[mi][3] = As[(ks*8 + t + 4)*KSTR + row + 8];
            }
            #pragma unroll
            for (int nt = 0; nt < 4; nt++) {
                int col = warp_n*32 + nt*8 + g;
                b[nt][0] = Bs[(ks*8 + t    )*KSTR + col];
                b[nt][1] = Bs[(ks*8 + t + 4)*KSTR + col];
            }
            #pragma unroll
            for (int mi = 0; mi < 4; mi++)
                #pragma unroll
                for (int nt = 0; nt < 4; nt++)
                    mma_tf32(acc[mi][nt], a[mi], b[nt]);
        }
        __syncthreads();
        if (kc < 15) {
            int kt = (kc+1)*32;
            #pragma unroll
            for (int l = 0; l < 4; l++) {
                uint32_t* d = As + (ka + l*8)*KSTR + p4;
                d[0] = f2tf32(pa[l].x); d[1] = f2tf32(pa[l].y);
                d[2] = f2tf32(pa[l].z); d[3] = f2tf32(pa[l].w);
            }
            #pragma unroll
            for (int l = 0; l < 4; l++) {
                int k = ka + l*8;
                float4 v = *(const float4*)(w2 + (size_t)(kt + k)*DIM + p4);
                uint32_t* d = Bs + k*KSTR + p4;
                d[0] = f2tf32(v.x); d[1] = f2tf32(v.y); d[2] = f2tf32(v.z); d[3] = f2tf32(v.w);
            }
            __syncthreads();
        }
    }
    #pragma unroll
    for (int mi = 0; mi < 4; mi++) {
        int row = warp_m*64 + mi*16 + g;
        #pragma unroll
        for (int nt = 0; nt < 4; nt++) {
            int col = warp_n*32 + nt*8 + 2*t;
            float b0v = b2[col], b1v = b2[col + 1];
            ts[row*TSTR + col]       = acc[mi][nt][0] + b0v;
            ts[row*TSTR + col + 1]   = acc[mi][nt][1] + b1v;
            ts[(row+8)*TSTR + col]   = acc[mi][nt][2] + b0v;
            ts[(row+8)*TSTR + col+1] = acc[mi][nt][3] + b1v;
        }
    }
    __syncthreads();
    #pragma unroll
    for (int l = 0; l < 64; l++) {
        int i = tid + l*256;
        int n = i >> 7, p = i & 127;
        g_c2[(size_t)n*NP + p0 + p] = ts[p*TSTR + n];
    }
}

// ======================= BN2 + final =======================
__global__ void k_bn2_part() {
    int c = blockIdx.x, seg = blockIdx.y;
    const float* p = g_c2 + (size_t)c*NP + seg*8192;
    float s = 0.f, q = 0.f;
    for (int i = threadIdx.x; i < 8192; i += 256) { float v = p[i]; s += v; q += v*v; }
    __shared__ float ss[256], qs[256];
    ss[threadIdx.x] = s; qs[threadIdx.x] = q;
    __syncthreads();
    for (int st = 128; st > 0; st >>= 1) {
        if (threadIdx.x < st) { ss[threadIdx.x] += ss[threadIdx.x+st]; qs[threadIdx.x] += qs[threadIdx.x+st]; }
        __syncthreads();
    }
    if (threadIdx.x == 0) { g_bn2_sum[seg*DIM + c] = ss[0]; g_bn2_sq[seg*DIM + c] = qs[0]; }
}
__global__ void k_bn2_final(const float* __restrict__ g, const float* __restrict__ be) {
    int c = threadIdx.x;
    float s = 0.f, q = 0.f;
    #pragma unroll
    for (int i = 0; i < 8; i++) { s += g_bn2_sum[i*DIM + c]; q += g_bn2_sq[i*DIM + c]; }
    float mean = s * (1.0f/NP);
    float var  = q * (1.0f/NP) - mean*mean;
    float rstd = rsqrtf(var + 1e-5f);
    float sc = g[c] * rstd;
    g_scale2[c] = sc;
    g_shift2[c] = be[c] - mean * sc;
}
__global__ void k_final(const float* __restrict__ x, float* __restrict__ out) {
    int i = blockIdx.x * 256 + threadIdx.x;
    int b = i >> 21;
    int c = (i >> 14) & 127;
    int hw = i & 16383;
    float v = g_c2[(size_t)c*NP + (b<<14) + hw] * g_scale2[c] + g_shift2[c];
    out[i] = gelu_exact(x[i] + v);
}

// ================================ launch ================================
extern "C" void kernel_launch(void* const* d_in, const int* in_sizes, int n_in,
                              void* d_out, int out_size) {
    const float* x        = (const float*)d_in[0];
    const float* offset_w = (const float*)d_in[1];
    const float* offset_b = (const float*)d_in[2];
    const float* deform_w = (const float*)d_in[3];
    const float* dw_w     = (const float*)d_in[4];
    const float* dw_b     = (const float*)d_in[5];
    const float* dw2_w    = (const float*)d_in[6];
    const float* dw2_b    = (const float*)d_in[7];
    const float* bn1_g    = (const float*)d_in[8];
    const float* bn1_b    = (const float*)d_in[9];
    const float* w1       = (const float*)d_in[10];
    const float* b1       = (const float*)d_in[11];
    const float* w2       = (const float*)d_in[12];
    const float* b2       = (const float*)d_in[13];
    const float* bn2_g    = (const float*)d_in[14];
    const float* bn2_b    = (const float*)d_in[15];
    float* out = (float*)d_out;

    static int smem_set = 0;
    const int GSMEM = 128*TSTR*4;   // 66560 bytes
    if (!smem_set) {
        cudaFuncSetAttribute(k_gemm1, cudaFuncAttributeMaxDynamicSharedMemorySize, GSMEM);
        cudaFuncSetAttribute(k_gemm2, cudaFuncAttributeMaxDynamicSharedMemorySize, GSMEM);
        cudaFuncSetAttribute(k_conv_mma<18,1,0,0>, cudaFuncAttributeMaxDynamicSharedMemorySize, CONV_SMEM);
        cudaFuncSetAttribute(k_conv_mma<32,2,96,1>, cudaFuncAttributeMaxDynamicSharedMemorySize, CONV_SMEM);
        smem_set = 1;
    }

    float* goffp; cudaGetSymbolAddress((void**)&goffp, g_off);
    float* gyp;   cudaGetSymbolAddress((void**)&gyp, g_y);

    dim3 blk256(256);
    k_conv_mma<18,1,0,0> <<<dim3(128, BATCH), blk256, CONV_SMEM>>>(x, offset_w, offset_b, goffp);
    k_conv_mma<32,2,96,1><<<dim3(128, BATCH), blk256, CONV_SMEM>>>(x, dw2_w, dw2_b, gyp);
    k_dw7_v2   <<<dim3(32, GC2, BATCH), blk256>>>(x, dw_w, dw_b);
    k_deform_v2<<<dim3(64, 4, BATCH), blk256>>>(x, deform_w);

    k_bn1_part <<<BATCH*DIM, blk256>>>();
    k_bn1_final<<<1, DIM>>>(bn1_g, bn1_b);
    k_fold_w1  <<<1, HID>>>(w1, b1);

    k_gemm1<<<dim3(HID/128, NP/128), 256, GSMEM>>>();
    k_gemm2<<<NP/128, 256, GSMEM>>>(w2, b2);

    k_bn2_part <<<dim3(DIM, 8), blk256>>>();
    k_bn2_final<<<1, DIM>>>(bn2_g, bn2_b);

    k_final<<<(size_t)NP*DIM/256, blk256>>>(x, out);
}

// round 6
// speedup vs baseline: 2.8927x; 1.0907x over previous
#include <cuda_runtime.h>
#include <cuda_bf16.h>
#include <math.h>
#include <stdint.h>

#define BATCH 4
#define DIM 128
#define HH 128
#define WW 128
#define HW (HH*WW)           // 16384
#define NP (BATCH*HW)        // 65536
#define HID 512
#define GC1 32
#define GC2 64
#define GC3 32

// ---------------- scratch ----------------
__device__ float g_off[BATCH*18*HW];
__device__ float g_y[BATCH*DIM*HW];            // shuffled concat, NCHW
__device__ float g_t[(size_t)HID*NP];          // GEMM1 out, TRANSPOSED [HID][NP]
__device__ float g_c2[(size_t)DIM*NP];         // GEMM2 out, TRANSPOSED [DIM][NP]
__device__ float g_b1f[HID];
__device__ float g_bn1_sum[BATCH*DIM];
__device__ float g_bn1_sq [BATCH*DIM];
__device__ float g_scale1[DIM], g_shift1[DIM];
__device__ float g_bn2_sum[512*DIM];
__device__ float g_bn2_sq [512*DIM];
__device__ float g_scale2[DIM], g_shift2[DIM];

__device__ __forceinline__ float gelu_exact(float v) {
    return 0.5f * v * (1.0f + erff(v * 0.70710678118654752440f));
}
__device__ __forceinline__ uint32_t f2tf32(float f) {
    uint32_t r;
    asm("cvt.rna.tf32.f32 %0, %1;" : "=r"(r) : "f"(f));
    return r;
}
__device__ __forceinline__ void mma_tf32(float* c, const uint32_t* a, const uint32_t* b) {
    asm volatile("mma.sync.aligned.m16n8k8.row.col.f32.tf32.tf32.f32 "
        "{%0,%1,%2,%3}, {%4,%5,%6,%7}, {%8,%9}, {%0,%1,%2,%3};"
        : "+f"(c[0]), "+f"(c[1]), "+f"(c[2]), "+f"(c[3])
        : "r"(a[0]), "r"(a[1]), "r"(a[2]), "r"(a[3]), "r"(b[0]), "r"(b[1]));
}

#define KSTR 136   // GEMM smem row stride
#define TSTR 130   // epilogue transpose stride

// ======================= implicit-GEMM tensor conv =======================
#define ASTR 136
#define BSTR 40
#define CONV_SMEM ((96*ASTR + 288*BSTR)*4)   // 98304 bytes

template<int NOC, int D, int CBASE, int MODE>
__global__ __launch_bounds__(256) void k_conv_mma(const float* __restrict__ x,
                                                  const float* __restrict__ w,
                                                  const float* __restrict__ bias,
                                                  float* __restrict__ outp) {
    extern __shared__ uint32_t cs[];
    uint32_t* As = cs;               // [96][ASTR]
    uint32_t* Bs = cs + 96*ASTR;     // [288][BSTR]
    int tid = threadIdx.x;
    int lane = tid & 31, wid = tid >> 5;
    int g = lane >> 2, t = lane & 3;
    int warp_m = wid >> 1, warp_n = wid & 1;
    int y = blockIdx.x, b = blockIdx.y;

    for (int i = tid; i < 96*ASTR; i += 256) {
        int r = i / ASTR, c = i - r*ASTR;
        int ky = r >> 5, ic = r & 31;
        int ry = y + (ky - 1)*D;
        int gx = c - D;
        float v = 0.f;
        if (ry >= 0 && ry < 128 && gx >= 0 && gx < 128)
            v = x[(((size_t)b*DIM + CBASE + ic) << 14) + (ry << 7) + gx];
        As[i] = f2tf32(v);
    }
    for (int i = tid; i < 288*32; i += 256) {
        int k = i >> 5, oc = i & 31;
        int tap = k >> 5, ic = k & 31;
        float v = (oc < NOC) ? w[(oc*32 + ic)*9 + tap] : 0.f;
        Bs[k*BSTR + oc] = f2tf32(v);
    }
    __syncthreads();

    float acc[2][2][4] = {};
    int mbase = warp_m*32 + g;
    int nbase = warp_n*16 + g;
    #pragma unroll
    for (int tap = 0; tap < 9; tap++) {
        const int ky = tap / 3, kx = tap % 3;
        #pragma unroll
        for (int k8 = 0; k8 < 4; k8++) {
            int ar = ky*32 + k8*8 + t;
            int bk = tap*32 + k8*8 + t;
            uint32_t a[2][4], bb[2][2];
            #pragma unroll
            for (int mi = 0; mi < 2; mi++) {
                int col = mbase + mi*16 + kx*D;
                a[mi][0] = As[ar*ASTR + col];
                a[mi][1] = As[ar*ASTR + col + 8];
                a[mi][2] = As[(ar + 4)*ASTR + col];
                a[mi][3] = As[(ar + 4)*ASTR + col + 8];
            }
            #pragma unroll
            for (int nt = 0; nt < 2; nt++) {
                bb[nt][0] = Bs[bk*BSTR + nbase + nt*8];
                bb[nt][1] = Bs[(bk + 4)*BSTR + nbase + nt*8];
            }
            #pragma unroll
            for (int mi = 0; mi < 2; mi++)
                #pragma unroll
                for (int nt = 0; nt < 2; nt++)
                    mma_tf32(acc[mi][nt], a[mi], bb[nt]);
        }
    }
    #pragma unroll
    for (int mi = 0; mi < 2; mi++) {
        #pragma unroll
        for (int nt = 0; nt < 2; nt++) {
            int col = warp_n*16 + nt*8 + 2*t;
            #pragma unroll
            for (int cc = 0; cc < 2; cc++) {
                int oc = col + cc;
                if (oc >= NOC) continue;
                float bv = bias[oc];
                int px0 = warp_m*32 + mi*16 + g;
                size_t base;
                if (MODE == 0) base = (((size_t)b*18 + oc) << 14) + (y << 7);
                else           base = (((size_t)b*DIM + 65 + 2*oc) << 14) + (y << 7);
                outp[base + px0]     = acc[mi][nt][cc]     + bv;
                outp[base + px0 + 8] = acc[mi][nt][cc + 2] + bv;
            }
        }
    }
}

// ======================= other conv kernels =======================

// depthwise 7x7, smem-tiled.  grid (32, 64, 4)
__global__ __launch_bounds__(256) void k_dw7_v2(const float* __restrict__ x,
                                                const float* __restrict__ dww,
                                                const float* __restrict__ dwb) {
    __shared__ float s[22*38];
    __shared__ float w[49];
    int tid = threadIdx.x;
    int lx = tid & 31, lyq = tid >> 5;
    int b = blockIdx.z;
    int c = blockIdx.y;
    int ty0 = (blockIdx.x >> 2) * 16, tx0 = (blockIdx.x & 3) * 32;
    const float* xp = x + ((size_t)b*DIM + 32 + c)*HW;
    #pragma unroll 4
    for (int i = tid; i < 22*38; i += 256) {
        int sy = i / 38, sx = i % 38;
        int gy = ty0 + sy - 3, gx = tx0 + sx - 3;
        float v = 0.f;
        if (gy >= 0 && gy < 128 && gx >= 0 && gx < 128) v = xp[gy*WW + gx];
        s[i] = v;
    }
    if (tid < 49) w[tid] = dww[c*49 + tid];
    __syncthreads();
    float bias = dwb[c];
    int oldc = 32 + c;
    int newc = (oldc < 64) ? (2*oldc) : (2*(oldc-64)+1);
    float* yp = g_y + ((size_t)b*DIM + newc)*HW;
    #pragma unroll
    for (int q = 0; q < 2; q++) {
        int ly = lyq + q*8;
        const float* sp = s + ly*38 + lx;
        float acc = bias;
        #pragma unroll
        for (int ky = 0; ky < 7; ky++)
            #pragma unroll
            for (int kx = 0; kx < 7; kx++)
                acc += sp[ky*38 + kx] * w[ky*7 + kx];
        yp[(ty0+ly)*WW + tx0+lx] = acc;
    }
}

// deformable depthwise v3: tap-outer, 8 channels inner (low regs, high MLP)
// grid (64, 4, 4)
__global__ __launch_bounds__(256) void k_deform_v3(const float* __restrict__ x,
                                                   const float* __restrict__ dfw) {
    __shared__ float wk[8][9];
    int tid = threadIdx.x;
    int b = blockIdx.z;
    int c0 = blockIdx.y * 8;
    int hw = blockIdx.x * 256 + tid;
    if (tid < 72) wk[tid/9][tid%9] = dfw[(c0 + tid/9)*9 + tid%9];
    __syncthreads();
    int h = hw >> 7, wc = hw & 127;
    const float* offb = g_off + (size_t)b*18*HW + hw;
    const float* xb = x + (((size_t)b*DIM + c0) << 14);
    float acc[8] = {};
    #pragma unroll
    for (int k = 0; k < 9; k++) {
        float dy = offb[(2*k  )*HW];
        float dx = offb[(2*k+1)*HW];
        float ys = (float)h - 1.0f + (float)(k/3) + dy;
        float xs = (float)wc - 1.0f + (float)(k%3) + dx;
        float y0 = floorf(ys), x0 = floorf(xs);
        float fy = ys - y0, fx = xs - x0;
        float vy0 = (y0 >= 0.f && y0 <= 127.f) ? 1.f : 0.f;
        float vy1 = (y0 >= -1.f && y0 <= 126.f) ? 1.f : 0.f;
        float vx0 = (x0 >= 0.f && x0 <= 127.f) ? 1.f : 0.f;
        float vx1 = (x0 >= -1.f && x0 <= 126.f) ? 1.f : 0.f;
        float w00 = (1.f-fy)*(1.f-fx) * vy0*vx0;
        float w01 = (1.f-fy)*fx       * vy0*vx1;
        float w10 = fy*(1.f-fx)       * vy1*vx0;
        float w11 = fy*fx             * vy1*vx1;
        int yi0 = min(max((int)y0, 0), 127);
        int yi1 = min(max((int)y0 + 1, 0), 127);
        int xi0 = min(max((int)x0, 0), 127);
        int xi1 = min(max((int)x0 + 1, 0), 127);
        int i00 = yi0*128 + xi0;
        int i01 = yi0*128 + xi1;
        int i10 = yi1*128 + xi0;
        int i11 = yi1*128 + xi1;
        #pragma unroll
        for (int cl = 0; cl < 8; cl++) {
            const float* xp = xb + (cl << 14);
            float sv = w00*xp[i00] + w01*xp[i01] + w10*xp[i10] + w11*xp[i11];
            acc[cl] += sv * wk[cl][k];
        }
    }
    #pragma unroll
    for (int cl = 0; cl < 8; cl++)
        g_y[(((size_t)b*DIM + 2*(c0+cl)) << 14) + hw] = acc[cl];
}

// ======================= BN1 + bias folding =======================
__global__ void k_bn1_part() {
    int bc = blockIdx.x;
    const float* p = g_y + (size_t)bc*HW;
    float s = 0.f, q = 0.f;
    for (int i = threadIdx.x; i < HW; i += 256) { float v = p[i]; s += v; q += v*v; }
    __shared__ float ss[256], qs[256];
    ss[threadIdx.x] = s; qs[threadIdx.x] = q;
    __syncthreads();
    for (int st = 128; st > 0; st >>= 1) {
        if (threadIdx.x < st) { ss[threadIdx.x] += ss[threadIdx.x+st]; qs[threadIdx.x] += qs[threadIdx.x+st]; }
        __syncthreads();
    }
    if (threadIdx.x == 0) { g_bn1_sum[bc] = ss[0]; g_bn1_sq[bc] = qs[0]; }
}
__global__ void k_bn1_final(const float* __restrict__ g, const float* __restrict__ be) {
    int c = threadIdx.x;
    float s = 0.f, q = 0.f;
    #pragma unroll
    for (int b = 0; b < BATCH; b++) { s += g_bn1_sum[b*DIM + c]; q += g_bn1_sq[b*DIM + c]; }
    float mean = s * (1.0f/NP);
    float var  = q * (1.0f/NP) - mean*mean;
    float rstd = rsqrtf(var + 1e-5f);
    float sc = g[c] * rstd;
    g_scale1[c] = sc;
    g_shift1[c] = be[c] - mean * sc;
}
// bias fold only: b1f[n] = b1[n] + sum_k shift1[k]*w1[k][n].  grid 4 x 128
__global__ void k_fold_b1(const float* __restrict__ w1, const float* __restrict__ b1) {
    int n = blockIdx.x * 128 + threadIdx.x;
    float bf = b1[n];
    for (int k = 0; k < DIM; k++)
        bf += g_shift1[k] * w1[k*HID + n];
    g_b1f[n] = bf;
}

// ======================= tf32 mma.sync GEMMs =======================
// GEMM1: A = BN1(g_y) (scale applied at fill), B = w1.  out -> g_t [HID][NP], gelu.
__global__ __launch_bounds__(256) void k_gemm1(const float* __restrict__ w1) {
    extern __shared__ uint32_t sm4[];
    uint32_t* As = sm4;
    uint32_t* Bs = sm4 + 32*KSTR;
    float* ts = (float*)sm4;
    int tid = threadIdx.x;
    int lane = tid & 31, wid = tid >> 5;
    int g = lane >> 2, t = lane & 3;
    int warp_m = wid >> 2, warp_n = wid & 3;
    int p0 = blockIdx.y * 128, n0 = blockIdx.x * 128;
    int cb = (p0 >> 14) * DIM;
    int hw0 = p0 & (HW-1);

    int ka = tid >> 5, p4 = (tid & 31) << 2;
    float acc[4][4][4] = {};
    {
        #pragma unroll
        for (int l = 0; l < 4; l++) {
            int k = ka + l*8;
            float sc = g_scale1[k];
            float4 v = *(const float4*)(g_y + (size_t)(cb + k)*HW + hw0 + p4);
            uint32_t* d = As + k*KSTR + p4;
            d[0] = f2tf32(v.x*sc); d[1] = f2tf32(v.y*sc); d[2] = f2tf32(v.z*sc); d[3] = f2tf32(v.w*sc);
        }
        #pragma unroll
        for (int l = 0; l < 4; l++) {
            int k = ka + l*8;
            float4 v = *(const float4*)(w1 + (size_t)k*HID + n0 + p4);
            uint32_t* d = Bs + k*KSTR + p4;
            d[0] = f2tf32(v.x); d[1] = f2tf32(v.y); d[2] = f2tf32(v.z); d[3] = f2tf32(v.w);
        }
    }
    __syncthreads();
    for (int kc = 0; kc < 4; kc++) {
        float4 pa[4];
        if (kc < 3) {
            int kt = (kc+1)*32;
            #pragma unroll
            for (int l = 0; l < 4; l++)
                pa[l] = *(const float4*)(g_y + (size_t)(cb + kt + ka + l*8)*HW + hw0 + p4);
        }
        #pragma unroll
        for (int ks = 0; ks < 4; ks++) {
            uint32_t a[4][4], b[4][2];
            #pragma unroll
            for (int mi = 0; mi < 4; mi++) {
                int row = warp_m*64 + mi*16 + g;
                a[mi][0] = As[(ks*8 + t    )*KSTR + row];
                a[mi][1] = As[(ks*8 + t    )*KSTR + row + 8];
                a[mi][2] = As[(ks*8 + t + 4)*KSTR + row];
                a[mi][3] = As[(ks*8 + t + 4)*KSTR + row + 8];
            }
            #pragma unroll
            for (int nt = 0; nt < 4; nt++) {
                int col = warp_n*32 + nt*8 + g;
                b[nt][0] = Bs[(ks*8 + t    )*KSTR + col];
                b[nt][1] = Bs[(ks*8 + t + 4)*KSTR + col];
            }
            #pragma unroll
            for (int mi = 0; mi < 4; mi++)
                #pragma unroll
                for (int nt = 0; nt < 4; nt++)
                    mma_tf32(acc[mi][nt], a[mi], b[nt]);
        }
        __syncthreads();
        if (kc < 3) {
            int kt = (kc+1)*32;
            #pragma unroll
            for (int l = 0; l < 4; l++) {
                float sc = g_scale1[kt + ka + l*8];
                uint32_t* d = As + (ka + l*8)*KSTR + p4;
                d[0] = f2tf32(pa[l].x*sc); d[1] = f2tf32(pa[l].y*sc);
                d[2] = f2tf32(pa[l].z*sc); d[3] = f2tf32(pa[l].w*sc);
            }
            #pragma unroll
            for (int l = 0; l < 4; l++) {
                int k = ka + l*8;
                float4 v = *(const float4*)(w1 + (size_t)(kt + k)*HID + n0 + p4);
                uint32_t* d = Bs + k*KSTR + p4;
                d[0] = f2tf32(v.x); d[1] = f2tf32(v.y); d[2] = f2tf32(v.z); d[3] = f2tf32(v.w);
            }
            __syncthreads();
        }
    }
    #pragma unroll
    for (int mi = 0; mi < 4; mi++) {
        int row = warp_m*64 + mi*16 + g;
        #pragma unroll
        for (int nt = 0; nt < 4; nt++) {
            int col = warp_n*32 + nt*8 + 2*t;
            float b0v = g_b1f[n0 + col], b1v = g_b1f[n0 + col + 1];
            ts[row*TSTR + col]       = gelu_exact(acc[mi][nt][0] + b0v);
            ts[row*TSTR + col + 1]   = gelu_exact(acc[mi][nt][1] + b1v);
            ts[(row+8)*TSTR + col]   = gelu_exact(acc[mi][nt][2] + b0v);
            ts[(row+8)*TSTR + col+1] = gelu_exact(acc[mi][nt][3] + b1v);
        }
    }
    __syncthreads();
    #pragma unroll
    for (int l = 0; l < 64; l++) {
        int i = tid + l*256;
        int n = i >> 7, p = i & 127;
        g_t[(size_t)(n0 + n)*NP + p0 + p] = ts[p*TSTR + n];
    }
}

// GEMM2 + fused BN2 partials
__global__ __launch_bounds__(256) void k_gemm2(const float* __restrict__ w2,
                                               const float* __restrict__ b2) {
    extern __shared__ uint32_t sm4[];
    uint32_t* As = sm4;
    uint32_t* Bs = sm4 + 32*KSTR;
    float* ts = (float*)sm4;
    __shared__ float rs[256], rq[256];
    int tid = threadIdx.x;
    int lane = tid & 31, wid = tid >> 5;
    int g = lane >> 2, t = lane & 3;
    int warp_m = wid >> 2, warp_n = wid & 3;
    int p0 = blockIdx.x * 128;

    int ka = tid >> 5, p4 = (tid & 31) << 2;
    float acc[4][4][4] = {};
    {
        #pragma unroll
        for (int l = 0; l < 4; l++) {
            int k = ka + l*8;
            float4 v = *(const float4*)(g_t + (size_t)k*NP + p0 + p4);
            uint32_t* d = As + k*KSTR + p4;
            d[0] = f2tf32(v.x); d[1] = f2tf32(v.y); d[2] = f2tf32(v.z); d[3] = f2tf32(v.w);
        }
        #pragma unroll
        for (int l = 0; l < 4; l++) {
            int k = ka + l*8;
            float4 v = *(const float4*)(w2 + (size_t)k*DIM + p4);
            uint32_t* d = Bs + k*KSTR + p4;
            d[0] = f2tf32(v.x); d[1] = f2tf32(v.y); d[2] = f2tf32(v.z); d[3] = f2tf32(v.w);
        }
    }
    __syncthreads();
    for (int kc = 0; kc < 16; kc++) {
        float4 pa[4];
        if (kc < 15) {
            int kt = (kc+1)*32;
            #pragma unroll
            for (int l = 0; l < 4; l++)
                pa[l] = *(const float4*)(g_t + (size_t)(kt + ka + l*8)*NP + p0 + p4);
        }
        #pragma unroll
        for (int ks = 0; ks < 4; ks++) {
            uint32_t a[4][4], b[4][2];
            #pragma unroll
            for (int mi = 0; mi < 4; mi++) {
                int row = warp_m*64 + mi*16 + g;
                a[mi][0] = As[(ks*8 + t    )*KSTR + row];
                a[mi][1] = As[(ks*8 + t    )*KSTR + row + 8];
                a[mi][2] = As[(ks*8 + t + 4)*KSTR + row];
                a[mi][3] = As[(ks*8 + t + 4)*KSTR + row + 8];
            }
            #pragma unroll
            for (int nt = 0; nt < 4; nt++) {
                int col = warp_n*32 + nt*8 + g;
                b[nt][0] = Bs[(ks*8 + t    )*KSTR + col];
                b[nt][1] = Bs[(ks*8 + t + 4)*KSTR + col];
            }
            #pragma unroll
            for (int mi = 0; mi < 4; mi++)
                #pragma unroll
                for (int nt = 0; nt < 4; nt++)
                    mma_tf32(acc[mi][nt], a[mi], b[nt]);
        }
        __syncthreads();
        if (kc < 15) {
            int kt = (kc+1)*32;
            #pragma unroll
            for (int l = 0; l < 4; l++) {
                uint32_t* d = As + (ka + l*8)*KSTR + p4;
                d[0] = f2tf32(pa[l].x); d[1] = f2tf32(pa[l].y);
                d[2] = f2tf32(pa[l].z); d[3] = f2tf32(pa[l].w);
            }
            #pragma unroll
            for (int l = 0; l < 4; l++) {
                int k = ka + l*8;
                float4 v = *(const float4*)(w2 + (size_t)(kt + k)*DIM + p4);
                uint32_t* d = Bs + k*KSTR + p4;
                d[0] = f2tf32(v.x); d[1] = f2tf32(v.y); d[2] = f2tf32(v.z); d[3] = f2tf32(v.w);
            }
            __syncthreads();
        }
    }
    #pragma unroll
    for (int mi = 0; mi < 4; mi++) {
        int row = warp_m*64 + mi*16 + g;
        #pragma unroll
        for (int nt = 0; nt < 4; nt++) {
            int col = warp_n*32 + nt*8 + 2*t;
            float b0v = b2[col], b1v = b2[col + 1];
            ts[row*TSTR + col]       = acc[mi][nt][0] + b0v;
            ts[row*TSTR + col + 1]   = acc[mi][nt][1] + b1v;
            ts[(row+8)*TSTR + col]   = acc[mi][nt][2] + b0v;
            ts[(row+8)*TSTR + col+1] = acc[mi][nt][3] + b1v;
        }
    }
    __syncthreads();
    #pragma unroll
    for (int l = 0; l < 64; l++) {
        int i = tid + l*256;
        int n = i >> 7, p = i & 127;
        g_c2[(size_t)n*NP + p0 + p] = ts[p*TSTR + n];
    }
    // fused BN2 partials over this 128x128 tile
    {
        int n = tid & 127;
        int ph = tid >> 7;
        float s = 0.f, q = 0.f;
        for (int p = ph; p < 128; p += 2) {
            float v = ts[p*TSTR + n];
            s += v; q += v*v;
        }
        rs[tid] = s; rq[tid] = q;
        __syncthreads();
        if (tid < 128) {
            g_bn2_sum[blockIdx.x*128 + tid] = rs[tid] + rs[tid+128];
            g_bn2_sq [blockIdx.x*128 + tid] = rq[tid] + rq[tid+128];
        }
    }
}

// ======================= BN2 final + output =======================
__global__ void k_bn2_final(const float* __restrict__ g, const float* __restrict__ be) {
    int c = blockIdx.x;
    int tid = threadIdx.x;
    __shared__ float ss[128], qs[128];
    float s = 0.f, q = 0.f;
    for (int i = tid; i < 512; i += 128) {
        s += g_bn2_sum[i*128 + c];
        q += g_bn2_sq [i*128 + c];
    }
    ss[tid] = s; qs[tid] = q;
    __syncthreads();
    for (int st = 64; st > 0; st >>= 1) {
        if (tid < st) { ss[tid] += ss[tid+st]; qs[tid] += qs[tid+st]; }
        __syncthreads();
    }
    if (tid == 0) {
        float mean = ss[0] * (1.0f/NP);
        float var  = qs[0] * (1.0f/NP) - mean*mean;
        float rstd = rsqrtf(var + 1e-5f);
        float sc = g[c] * rstd;
        g_scale2[c] = sc;
        g_shift2[c] = be[c] - mean * sc;
    }
}
__global__ void k_final(const float* __restrict__ x, float* __restrict__ out) {
    int i = blockIdx.x * 256 + threadIdx.x;
    int b = i >> 21;
    int c = (i >> 14) & 127;
    int hw = i & 16383;
    float v = g_c2[(size_t)c*NP + (b<<14) + hw] * g_scale2[c] + g_shift2[c];
    out[i] = gelu_exact(x[i] + v);
}

// ================================ launch ================================
extern "C" void kernel_launch(void* const* d_in, const int* in_sizes, int n_in,
                              void* d_out, int out_size) {
    const float* x        = (const float*)d_in[0];
    const float* offset_w = (const float*)d_in[1];
    const float* offset_b = (const float*)d_in[2];
    const float* deform_w = (const float*)d_in[3];
    const float* dw_w     = (const float*)d_in[4];
    const float* dw_b     = (const float*)d_in[5];
    const float* dw2_w    = (const float*)d_in[6];
    const float* dw2_b    = (const float*)d_in[7];
    const float* bn1_g    = (const float*)d_in[8];
    const float* bn1_b    = (const float*)d_in[9];
    const float* w1       = (const float*)d_in[10];
    const float* b1       = (const float*)d_in[11];
    const float* w2       = (const float*)d_in[12];
    const float* b2       = (const float*)d_in[13];
    const float* bn2_g    = (const float*)d_in[14];
    const float* bn2_b    = (const float*)d_in[15];
    float* out = (float*)d_out;

    static int inited = 0;
    static cudaStream_t sA, sB, sC;
    static cudaEvent_t e0, eA, eB, eC;
    const int GSMEM = 128*TSTR*4;   // 66560 bytes
    if (!inited) {
        cudaFuncSetAttribute(k_gemm1, cudaFuncAttributeMaxDynamicSharedMemorySize, GSMEM);
        cudaFuncSetAttribute(k_gemm2, cudaFuncAttributeMaxDynamicSharedMemorySize, GSMEM);
        cudaFuncSetAttribute(k_conv_mma<18,1,0,0>, cudaFuncAttributeMaxDynamicSharedMemorySize, CONV_SMEM);
        cudaFuncSetAttribute(k_conv_mma<32,2,96,1>, cudaFuncAttributeMaxDynamicSharedMemorySize, CONV_SMEM);
        cudaStreamCreateWithFlags(&sA, cudaStreamNonBlocking);
        cudaStreamCreateWithFlags(&sB, cudaStreamNonBlocking);
        cudaStreamCreateWithFlags(&sC, cudaStreamNonBlocking);
        cudaEventCreateWithFlags(&e0, cudaEventDisableTiming);
        cudaEventCreateWithFlags(&eA, cudaEventDisableTiming);
        cudaEventCreateWithFlags(&eB, cudaEventDisableTiming);
        cudaEventCreateWithFlags(&eC, cudaEventDisableTiming);
        inited = 1;
    }

    float* goffp; cudaGetSymbolAddress((void**)&goffp, g_off);
    float* gyp;   cudaGetSymbolAddress((void**)&gyp, g_y);

    dim3 blk256(256);
    // fork: three independent conv branches
    cudaEventRecord(e0, 0);
    cudaStreamWaitEvent(sA, e0, 0);
    k_conv_mma<18,1,0,0> <<<dim3(128, BATCH), blk256, CONV_SMEM, sA>>>(x, offset_w, offset_b, goffp);
    k_deform_v3          <<<dim3(64, 4, BATCH), blk256, 0, sA>>>(x, deform_w);
    cudaEventRecord(eA, sA);
    cudaStreamWaitEvent(sB, e0, 0);
    k_conv_mma<32,2,96,1><<<dim3(128, BATCH), blk256, CONV_SMEM, sB>>>(x, dw2_w, dw2_b, gyp);
    cudaEventRecord(eB, sB);
    cudaStreamWaitEvent(sC, e0, 0);
    k_dw7_v2             <<<dim3(32, GC2, BATCH), blk256, 0, sC>>>(x, dw_w, dw_b);
    cudaEventRecord(eC, sC);
    // join on default stream
    cudaStreamWaitEvent(0, eA, 0);
    cudaStreamWaitEvent(0, eB, 0);
    cudaStreamWaitEvent(0, eC, 0);

    k_bn1_part <<<BATCH*DIM, blk256>>>();
    k_bn1_final<<<1, DIM>>>(bn1_g, bn1_b);
    k_fold_b1  <<<4, 128>>>(w1, b1);

    k_gemm1<<<dim3(HID/128, NP/128), 256, GSMEM>>>(w1);
    k_gemm2<<<NP/128, 256, GSMEM>>>(w2, b2);

    k_bn2_final<<<DIM, 128>>>(bn2_g, bn2_b);
    k_final<<<(size_t)NP*DIM/256, blk256>>>(x, out);
}